// round 1
// baseline (speedup 1.0000x reference)
#include <cuda_runtime.h>
#include <math.h>

#define N_NODES   100000
#define N_EDGES   1600000
#define N_GRAPHS  64
#define F_IN      256
#define F_HID     128
#define NEG_SLOPE 0.01f

// ---------------- scratch (no allocations allowed) ----------------
__device__ float g_h[(size_t)N_NODES * F_HID];   // GEMM output
__device__ float g_a[(size_t)N_NODES * F_HID];   // aggregation output / next GEMM input
__device__ int   g_deg[N_NODES];
__device__ int   g_fill[N_NODES];
__device__ float g_dinv[N_NODES];
__device__ int   g_rowptr[N_NODES + 1];
__device__ int   g_csrc[N_EDGES];
__device__ float g_pool[N_GRAPHS * F_HID];
__device__ float g_cnt[N_GRAPHS];

// ---------------- utility: zero all per-launch accumulators ----------------
__global__ void zero_kernel() {
    int i = blockIdx.x * blockDim.x + threadIdx.x;
    if (i < N_NODES) { g_deg[i] = 0; g_fill[i] = 0; }
    if (i < N_GRAPHS * F_HID) g_pool[i] = 0.0f;
    if (i < N_GRAPHS) g_cnt[i] = 0.0f;
}

// ---------------- degree (in-degree over dst) ----------------
__global__ void degree_kernel(const int* __restrict__ dst) {
    int e = blockIdx.x * blockDim.x + threadIdx.x;
    if (e < N_EDGES) atomicAdd(&g_deg[dst[e]], 1);
}

__global__ void dinv_kernel() {
    int i = blockIdx.x * blockDim.x + threadIdx.x;
    if (i < N_NODES) g_dinv[i] = rsqrtf((float)g_deg[i] + 1.0f);
}

// ---------------- exclusive scan of degrees -> rowptr (single block) ----------------
__global__ void scan_kernel() {
    __shared__ int sums[1024];
    const int n = N_NODES;
    int t = threadIdx.x;
    int chunk = (n + 1023) / 1024;
    int beg = t * chunk;
    int end = min(beg + chunk, n);
    int s = 0;
    for (int i = beg; i < end; i++) s += g_deg[i];
    sums[t] = s;
    __syncthreads();
    // Hillis-Steele inclusive scan
    for (int off = 1; off < 1024; off <<= 1) {
        int v = (t >= off) ? sums[t - off] : 0;
        __syncthreads();
        sums[t] += v;
        __syncthreads();
    }
    int offset = (t == 0) ? 0 : sums[t - 1];
    int run = offset;
    for (int i = beg; i < end; i++) { g_rowptr[i] = run; run += g_deg[i]; }
    if (end == n) g_rowptr[n] = run;   // == N_EDGES
}

// ---------------- CSR fill ----------------
__global__ void csr_fill_kernel(const int* __restrict__ src, const int* __restrict__ dst) {
    int e = blockIdx.x * blockDim.x + threadIdx.x;
    if (e < N_EDGES) {
        int d = dst[e];
        int pos = g_rowptr[d] + atomicAdd(&g_fill[d], 1);
        g_csrc[pos] = src[e];
    }
}

// ---------------- SGEMM: C[M,128] = A[M,K] @ B[K,128] ----------------
// BM=64, BN=128, BK=16, 256 threads, each thread computes 4x8.
__global__ __launch_bounds__(256) void gemm_kernel(
    const float* __restrict__ A, const float* __restrict__ B,
    float* __restrict__ C, int M, int K)
{
    __shared__ float As[16][64];
    __shared__ float Bs[16][128];
    int tid = threadIdx.x;
    int block_m = blockIdx.x * 64;
    int tx = tid & 15;   // N: 16 groups of 8
    int ty = tid >> 4;   // M: 16 groups of 4
    float acc[4][8];
    #pragma unroll
    for (int i = 0; i < 4; i++)
        #pragma unroll
        for (int j = 0; j < 8; j++) acc[i][j] = 0.0f;

    for (int k0 = 0; k0 < K; k0 += 16) {
        // load A tile (64 x 16), transposed into As[k][m]
        int a_row = tid >> 2;         // 0..63
        int a_k   = (tid & 3) << 2;   // 0,4,8,12
        float4 av = make_float4(0.f, 0.f, 0.f, 0.f);
        int gm = block_m + a_row;
        if (gm < M) av = *(const float4*)(A + (size_t)gm * K + k0 + a_k);
        As[a_k + 0][a_row] = av.x;
        As[a_k + 1][a_row] = av.y;
        As[a_k + 2][a_row] = av.z;
        As[a_k + 3][a_row] = av.w;
        // load B tile (16 x 128)
        #pragma unroll
        for (int r = 0; r < 2; r++) {
            int idx = tid + r * 256;
            int b_row = idx >> 5;          // 0..15
            int b_col = (idx & 31) << 2;   // 0..124
            *(float4*)&Bs[b_row][b_col] =
                *(const float4*)(B + (size_t)(k0 + b_row) * 128 + b_col);
        }
        __syncthreads();
        #pragma unroll
        for (int kk = 0; kk < 16; kk++) {
            float4 ra  = *(const float4*)&As[kk][ty * 4];
            float4 rb0 = *(const float4*)&Bs[kk][tx * 8];
            float4 rb1 = *(const float4*)&Bs[kk][tx * 8 + 4];
            float ram[4] = {ra.x, ra.y, ra.z, ra.w};
            float rbm[8] = {rb0.x, rb0.y, rb0.z, rb0.w, rb1.x, rb1.y, rb1.z, rb1.w};
            #pragma unroll
            for (int i = 0; i < 4; i++)
                #pragma unroll
                for (int j = 0; j < 8; j++)
                    acc[i][j] = fmaf(ram[i], rbm[j], acc[i][j]);
        }
        __syncthreads();
    }
    #pragma unroll
    for (int i = 0; i < 4; i++) {
        int gm = block_m + ty * 4 + i;
        if (gm < M) {
            float4 v0 = make_float4(acc[i][0], acc[i][1], acc[i][2], acc[i][3]);
            float4 v1 = make_float4(acc[i][4], acc[i][5], acc[i][6], acc[i][7]);
            *(float4*)(C + (size_t)gm * 128 + tx * 8)     = v0;
            *(float4*)(C + (size_t)gm * 128 + tx * 8 + 4) = v1;
        }
    }
}

// ---------------- aggregation: one warp per node ----------------
// out[v] = leaky( dinv[v]^2 * h[v] + sum_{e in CSR row v} dinv[src]*dinv[v]*h[src] + bias )
__global__ __launch_bounds__(256) void aggregate_kernel(
    const float* __restrict__ h, const float* __restrict__ bias,
    float* __restrict__ out)
{
    int warp = (blockIdx.x * blockDim.x + threadIdx.x) >> 5;
    int lane = threadIdx.x & 31;
    if (warp >= N_NODES) return;
    float dv = g_dinv[warp];
    float4 hv = *(const float4*)(h + (size_t)warp * 128 + lane * 4);
    float s = dv * dv;
    float4 acc = make_float4(hv.x * s, hv.y * s, hv.z * s, hv.w * s);
    int beg = g_rowptr[warp], end = g_rowptr[warp + 1];
    for (int e = beg; e < end; e++) {
        int src = g_csrc[e];
        float w = g_dinv[src] * dv;
        float4 m = *(const float4*)(h + (size_t)src * 128 + lane * 4);
        acc.x = fmaf(m.x, w, acc.x);
        acc.y = fmaf(m.y, w, acc.y);
        acc.z = fmaf(m.z, w, acc.z);
        acc.w = fmaf(m.w, w, acc.w);
    }
    float4 bv = *(const float4*)(bias + lane * 4);
    acc.x += bv.x; acc.y += bv.y; acc.z += bv.z; acc.w += bv.w;
    acc.x = acc.x > 0.f ? acc.x : NEG_SLOPE * acc.x;
    acc.y = acc.y > 0.f ? acc.y : NEG_SLOPE * acc.y;
    acc.z = acc.z > 0.f ? acc.z : NEG_SLOPE * acc.z;
    acc.w = acc.w > 0.f ? acc.w : NEG_SLOPE * acc.w;
    *(float4*)(out + (size_t)warp * 128 + lane * 4) = acc;
}

// ---------------- global mean pool (sums + counts) ----------------
__global__ __launch_bounds__(256) void pool_kernel(
    const float* __restrict__ act, const int* __restrict__ batch)
{
    int warp = (blockIdx.x * blockDim.x + threadIdx.x) >> 5;
    int lane = threadIdx.x & 31;
    if (warp >= N_NODES) return;
    int g = batch[warp];
    float4 v = *(const float4*)(act + (size_t)warp * 128 + lane * 4);
    float* p = &g_pool[g * 128 + lane * 4];
    atomicAdd(p + 0, v.x);
    atomicAdd(p + 1, v.y);
    atomicAdd(p + 2, v.z);
    atomicAdd(p + 3, v.w);
    if (lane == 0) atomicAdd(&g_cnt[g], 1.0f);
}

// ---------------- final FC: [64,128] @ [128,2] + bfc ----------------
__global__ void fc_kernel(const float* __restrict__ Wfc, const float* __restrict__ bfc,
                          float* __restrict__ out)
{
    int t = threadIdx.x;           // 128 threads: t = g*2 + c
    if (t >= N_GRAPHS * 2) return;
    int g = t >> 1, c = t & 1;
    float inv = 1.0f / fmaxf(g_cnt[g], 1.0f);
    float sum = 0.0f;
    #pragma unroll 4
    for (int k = 0; k < 128; k++)
        sum = fmaf(g_pool[g * 128 + k] * inv, Wfc[k * 2 + c], sum);
    out[t] = sum + bfc[c];
}

// ---------------- launch ----------------
extern "C" void kernel_launch(void* const* d_in, const int* in_sizes, int n_in,
                              void* d_out, int out_size)
{
    const float* x   = (const float*)d_in[0];
    const int*   ei  = (const int*)d_in[1];
    const int*   bat = (const int*)d_in[2];
    const float* W1  = (const float*)d_in[3];
    const float* b1  = (const float*)d_in[4];
    const float* W2  = (const float*)d_in[5];
    const float* b2  = (const float*)d_in[6];
    const float* Wfc = (const float*)d_in[7];
    const float* bfc = (const float*)d_in[8];
    float* out = (float*)d_out;
    const int* src = ei;
    const int* dst = ei + N_EDGES;

    float *hptr, *aptr;
    cudaGetSymbolAddress((void**)&hptr, g_h);
    cudaGetSymbolAddress((void**)&aptr, g_a);

    const int TB = 256;
    int node_blocks = (N_NODES + TB - 1) / TB;
    int edge_blocks = (N_EDGES + TB - 1) / TB;
    int warp_blocks = (N_NODES * 32 + TB - 1) / TB;   // one warp per node
    int gemm_blocks = (N_NODES + 63) / 64;

    zero_kernel<<<node_blocks, TB>>>();
    degree_kernel<<<edge_blocks, TB>>>(dst);
    dinv_kernel<<<node_blocks, TB>>>();
    scan_kernel<<<1, 1024>>>();
    csr_fill_kernel<<<edge_blocks, TB>>>(src, dst);

    // layer 1
    gemm_kernel<<<gemm_blocks, TB>>>(x, W1, hptr, N_NODES, F_IN);
    aggregate_kernel<<<warp_blocks, TB>>>(hptr, b1, aptr);
    // layer 2
    gemm_kernel<<<gemm_blocks, TB>>>(aptr, W2, hptr, N_NODES, F_HID);
    aggregate_kernel<<<warp_blocks, TB>>>(hptr, b2, aptr);

    // pool + fc
    pool_kernel<<<warp_blocks, TB>>>(aptr, bat);
    fc_kernel<<<1, 128>>>(Wfc, bfc, out);
}

// round 2
// speedup vs baseline: 1.8560x; 1.8560x over previous
#include <cuda_runtime.h>
#include <math.h>

#define N_NODES   100000
#define N_EDGES   1600000
#define N_GRAPHS  64
#define F_IN      256
#define F_HID     128
#define NEG_SLOPE 0.01f

#define SCAN_B    1024
#define NB_SCAN   ((N_NODES + SCAN_B - 1) / SCAN_B)   // 98

// ---------------- scratch ----------------
__device__ float g_h[(size_t)N_NODES * F_HID];
__device__ float g_a[(size_t)N_NODES * F_HID];
__device__ int   g_deg[N_NODES];
__device__ int   g_fill[N_NODES];
__device__ float g_dinv[N_NODES];
__device__ int   g_rowptr[N_NODES + 1];
__device__ int   g_csrc[N_EDGES];
__device__ int   g_bsum[NB_SCAN];
__device__ int   g_boff[NB_SCAN];
__device__ int   g_gstart[N_GRAPHS + 1];
__device__ float g_pool[N_GRAPHS * F_HID];
__device__ float g_cnt[N_GRAPHS];

// ---------------- init ----------------
__global__ void zero_kernel() {
    int i = blockIdx.x * blockDim.x + threadIdx.x;
    if (i < N_NODES) { g_deg[i] = 0; g_fill[i] = 0; }
    if (i < N_GRAPHS + 1) g_gstart[i] = N_NODES;
}

// ---------------- degree ----------------
__global__ void degree_kernel(const int* __restrict__ dst) {
    int e = blockIdx.x * blockDim.x + threadIdx.x;
    if (e < N_EDGES) atomicAdd(&g_deg[dst[e]], 1);
}

__global__ void dinv_kernel() {
    int i = blockIdx.x * blockDim.x + threadIdx.x;
    if (i < N_NODES) g_dinv[i] = rsqrtf((float)g_deg[i] + 1.0f);
}

// ---------------- parallel exclusive scan: deg -> rowptr ----------------
__global__ __launch_bounds__(SCAN_B) void scan1_kernel() {   // per-block sums
    __shared__ int red[SCAN_B];
    int t = threadIdx.x;
    int i = blockIdx.x * SCAN_B + t;
    red[t] = (i < N_NODES) ? g_deg[i] : 0;
    __syncthreads();
    for (int off = SCAN_B / 2; off > 0; off >>= 1) {
        if (t < off) red[t] += red[t + off];
        __syncthreads();
    }
    if (t == 0) g_bsum[blockIdx.x] = red[0];
}

__global__ void scan2_kernel() {   // scan of 98 block sums (smem-resident)
    __shared__ int s[NB_SCAN];
    int t = threadIdx.x;
    if (t < NB_SCAN) s[t] = g_bsum[t];
    __syncthreads();
    if (t == 0) {
        int run = 0;
        for (int b = 0; b < NB_SCAN; b++) { int v = s[b]; s[b] = run; run += v; }
        g_rowptr[N_NODES] = N_EDGES;
    }
    __syncthreads();
    if (t < NB_SCAN) g_boff[t] = s[t];
}

__global__ __launch_bounds__(SCAN_B) void scan3_kernel() {   // per-block exclusive scan
    __shared__ int s[SCAN_B];
    int t = threadIdx.x;
    int i = blockIdx.x * SCAN_B + t;
    int v = (i < N_NODES) ? g_deg[i] : 0;
    s[t] = v;
    __syncthreads();
    for (int off = 1; off < SCAN_B; off <<= 1) {    // Hillis-Steele inclusive
        int u = (t >= off) ? s[t - off] : 0;
        __syncthreads();
        s[t] += u;
        __syncthreads();
    }
    if (i < N_NODES) g_rowptr[i] = g_boff[blockIdx.x] + s[t] - v;
}

// ---------------- CSR fill ----------------
__global__ void csr_fill_kernel(const int* __restrict__ src, const int* __restrict__ dst) {
    int e = blockIdx.x * blockDim.x + threadIdx.x;
    if (e < N_EDGES) {
        int d = dst[e];
        int pos = g_rowptr[d] + atomicAdd(&g_fill[d], 1);
        g_csrc[pos] = src[e];
    }
}

// ---------------- SGEMM: C[M,128] = A[M,K] @ B[K,128] ----------------
// 128x128 tile, BK=8, 256 threads, 8x8 microtile, double-buffered smem.
__global__ __launch_bounds__(256) void gemm_kernel(
    const float* __restrict__ A, const float* __restrict__ B,
    float* __restrict__ C, int M, int K)
{
    __shared__ float As[2][8][128];
    __shared__ float Bs[2][8][128];
    const int tid = threadIdx.x;
    const int block_m = blockIdx.x * 128;

    const int arow = tid >> 1;          // 0..127
    const int acol = (tid & 1) << 2;    // 0 or 4
    const int brow = tid >> 5;          // 0..7
    const int bcol = (tid & 31) << 2;   // 0..124
    const int m0 = (tid >> 4) << 3;     // 0..120
    const int n0 = (tid & 15) << 3;     // 0..120

    float acc[8][8];
    #pragma unroll
    for (int i = 0; i < 8; i++)
        #pragma unroll
        for (int j = 0; j < 8; j++) acc[i][j] = 0.0f;

    const int gm_a = block_m + arow;
    const float* Aptr = A + (size_t)gm_a * K + acol;
    const float* Bptr = B + (size_t)brow * 128 + bcol;

    // preload tile 0
    {
        float4 av = make_float4(0.f,0.f,0.f,0.f);
        if (gm_a < M) av = *(const float4*)(Aptr);
        As[0][acol+0][arow] = av.x;
        As[0][acol+1][arow] = av.y;
        As[0][acol+2][arow] = av.z;
        As[0][acol+3][arow] = av.w;
        *(float4*)&Bs[0][brow][bcol] = *(const float4*)(Bptr);
    }
    __syncthreads();

    int buf = 0;
    for (int k0 = 0; k0 < K; k0 += 8) {
        float4 av, bv;
        const bool more = (k0 + 8 < K);
        if (more) {
            av = make_float4(0.f,0.f,0.f,0.f);
            if (gm_a < M) av = *(const float4*)(Aptr + k0 + 8);
            bv = *(const float4*)(Bptr + (size_t)(k0 + 8) * 128);
        }
        #pragma unroll
        for (int kk = 0; kk < 8; kk++) {
            float4 a0 = *(const float4*)&As[buf][kk][m0];
            float4 a1 = *(const float4*)&As[buf][kk][m0 + 4];
            float4 b0 = *(const float4*)&Bs[buf][kk][n0];
            float4 b1 = *(const float4*)&Bs[buf][kk][n0 + 4];
            float am[8] = {a0.x,a0.y,a0.z,a0.w,a1.x,a1.y,a1.z,a1.w};
            float bm[8] = {b0.x,b0.y,b0.z,b0.w,b1.x,b1.y,b1.z,b1.w};
            #pragma unroll
            for (int i = 0; i < 8; i++)
                #pragma unroll
                for (int j = 0; j < 8; j++)
                    acc[i][j] = fmaf(am[i], bm[j], acc[i][j]);
        }
        if (more) {
            int nb = buf ^ 1;
            As[nb][acol+0][arow] = av.x;
            As[nb][acol+1][arow] = av.y;
            As[nb][acol+2][arow] = av.z;
            As[nb][acol+3][arow] = av.w;
            *(float4*)&Bs[nb][brow][bcol] = bv;
            __syncthreads();
            buf = nb;
        }
    }

    #pragma unroll
    for (int i = 0; i < 8; i++) {
        int gm = block_m + m0 + i;
        if (gm < M) {
            *(float4*)(C + (size_t)gm * 128 + n0) =
                make_float4(acc[i][0], acc[i][1], acc[i][2], acc[i][3]);
            *(float4*)(C + (size_t)gm * 128 + n0 + 4) =
                make_float4(acc[i][4], acc[i][5], acc[i][6], acc[i][7]);
        }
    }
}

// ---------------- aggregation: one warp per node, 4-way unrolled ----------------
__global__ __launch_bounds__(256) void aggregate_kernel(
    const float* __restrict__ h, const float* __restrict__ bias,
    float* __restrict__ out)
{
    int warp = (blockIdx.x * blockDim.x + threadIdx.x) >> 5;
    int lane = threadIdx.x & 31;
    if (warp >= N_NODES) return;
    float dv = g_dinv[warp];
    float4 hv = *(const float4*)(h + (size_t)warp * 128 + lane * 4);
    float s = dv * dv;
    float4 acc = make_float4(hv.x * s, hv.y * s, hv.z * s, hv.w * s);
    int e = g_rowptr[warp], end = g_rowptr[warp + 1];

    for (; e + 4 <= end; e += 4) {
        int s0 = g_csrc[e], s1 = g_csrc[e+1], s2 = g_csrc[e+2], s3 = g_csrc[e+3];
        float w0 = g_dinv[s0] * dv, w1 = g_dinv[s1] * dv;
        float w2 = g_dinv[s2] * dv, w3 = g_dinv[s3] * dv;
        float4 m0 = *(const float4*)(h + (size_t)s0 * 128 + lane * 4);
        float4 m1 = *(const float4*)(h + (size_t)s1 * 128 + lane * 4);
        float4 m2 = *(const float4*)(h + (size_t)s2 * 128 + lane * 4);
        float4 m3 = *(const float4*)(h + (size_t)s3 * 128 + lane * 4);
        acc.x = fmaf(m0.x, w0, acc.x); acc.y = fmaf(m0.y, w0, acc.y);
        acc.z = fmaf(m0.z, w0, acc.z); acc.w = fmaf(m0.w, w0, acc.w);
        acc.x = fmaf(m1.x, w1, acc.x); acc.y = fmaf(m1.y, w1, acc.y);
        acc.z = fmaf(m1.z, w1, acc.z); acc.w = fmaf(m1.w, w1, acc.w);
        acc.x = fmaf(m2.x, w2, acc.x); acc.y = fmaf(m2.y, w2, acc.y);
        acc.z = fmaf(m2.z, w2, acc.z); acc.w = fmaf(m2.w, w2, acc.w);
        acc.x = fmaf(m3.x, w3, acc.x); acc.y = fmaf(m3.y, w3, acc.y);
        acc.z = fmaf(m3.z, w3, acc.z); acc.w = fmaf(m3.w, w3, acc.w);
    }
    for (; e < end; e++) {
        int sv = g_csrc[e];
        float w = g_dinv[sv] * dv;
        float4 m = *(const float4*)(h + (size_t)sv * 128 + lane * 4);
        acc.x = fmaf(m.x, w, acc.x); acc.y = fmaf(m.y, w, acc.y);
        acc.z = fmaf(m.z, w, acc.z); acc.w = fmaf(m.w, w, acc.w);
    }
    float4 bv = *(const float4*)(bias + lane * 4);
    acc.x += bv.x; acc.y += bv.y; acc.z += bv.z; acc.w += bv.w;
    acc.x = acc.x > 0.f ? acc.x : NEG_SLOPE * acc.x;
    acc.y = acc.y > 0.f ? acc.y : NEG_SLOPE * acc.y;
    acc.z = acc.z > 0.f ? acc.z : NEG_SLOPE * acc.z;
    acc.w = acc.w > 0.f ? acc.w : NEG_SLOPE * acc.w;
    *(float4*)(out + (size_t)warp * 128 + lane * 4) = acc;
}

// ---------------- pool: sorted batch -> contiguous ranges ----------------
__global__ void boundary_kernel(const int* __restrict__ batch) {
    int i = blockIdx.x * blockDim.x + threadIdx.x;
    if (i < N_NODES) atomicMin(&g_gstart[batch[i]], i);
}

__global__ void boundary_fix_kernel() {   // backward min-propagate (smem-resident)
    __shared__ int s[N_GRAPHS + 1];
    int t = threadIdx.x;
    if (t < N_GRAPHS + 1) s[t] = g_gstart[t];
    __syncthreads();
    if (t == 0)
        for (int g = N_GRAPHS - 1; g >= 0; g--)
            if (s[g] > s[g + 1]) s[g] = s[g + 1];
    __syncthreads();
    if (t < N_GRAPHS + 1) g_gstart[t] = s[t];
}

__global__ __launch_bounds__(128) void pool_kernel(const float* __restrict__ act) {
    int g = blockIdx.x;         // one block per graph
    int t = threadIdx.x;        // feature index 0..127
    int beg = g_gstart[g], end = g_gstart[g + 1];
    float sum = 0.0f;
    int i = beg;
    for (; i + 4 <= end; i += 4) {
        float v0 = act[(size_t)(i+0) * 128 + t];
        float v1 = act[(size_t)(i+1) * 128 + t];
        float v2 = act[(size_t)(i+2) * 128 + t];
        float v3 = act[(size_t)(i+3) * 128 + t];
        sum += (v0 + v1) + (v2 + v3);
    }
    for (; i < end; i++) sum += act[(size_t)i * 128 + t];
    g_pool[g * 128 + t] = sum;
    if (t == 0) g_cnt[g] = (float)(end - beg);
}

// ---------------- final FC ----------------
__global__ void fc_kernel(const float* __restrict__ Wfc, const float* __restrict__ bfc,
                          float* __restrict__ out)
{
    int t = threadIdx.x;
    if (t >= N_GRAPHS * 2) return;
    int g = t >> 1, c = t & 1;
    float inv = 1.0f / fmaxf(g_cnt[g], 1.0f);
    float sum = 0.0f;
    #pragma unroll 4
    for (int k = 0; k < 128; k++)
        sum = fmaf(g_pool[g * 128 + k] * inv, Wfc[k * 2 + c], sum);
    out[t] = sum + bfc[c];
}

// ---------------- launch ----------------
extern "C" void kernel_launch(void* const* d_in, const int* in_sizes, int n_in,
                              void* d_out, int out_size)
{
    const float* x   = (const float*)d_in[0];
    const int*   ei  = (const int*)d_in[1];
    const int*   bat = (const int*)d_in[2];
    const float* W1  = (const float*)d_in[3];
    const float* b1  = (const float*)d_in[4];
    const float* W2  = (const float*)d_in[5];
    const float* b2  = (const float*)d_in[6];
    const float* Wfc = (const float*)d_in[7];
    const float* bfc = (const float*)d_in[8];
    float* out = (float*)d_out;
    const int* src = ei;
    const int* dst = ei + N_EDGES;

    float *hptr, *aptr;
    cudaGetSymbolAddress((void**)&hptr, g_h);
    cudaGetSymbolAddress((void**)&aptr, g_a);

    const int TB = 256;
    int node_blocks = (N_NODES + TB - 1) / TB;
    int edge_blocks = (N_EDGES + TB - 1) / TB;
    int warp_blocks = (N_NODES * 32 + TB - 1) / TB;
    int gemm_blocks = (N_NODES + 127) / 128;

    zero_kernel<<<node_blocks, TB>>>();
    degree_kernel<<<edge_blocks, TB>>>(dst);
    dinv_kernel<<<node_blocks, TB>>>();
    scan1_kernel<<<NB_SCAN, SCAN_B>>>();
    scan2_kernel<<<1, 128>>>();
    scan3_kernel<<<NB_SCAN, SCAN_B>>>();
    csr_fill_kernel<<<edge_blocks, TB>>>(src, dst);
    boundary_kernel<<<node_blocks, TB>>>(bat);
    boundary_fix_kernel<<<1, 128>>>();

    // layer 1
    gemm_kernel<<<gemm_blocks, TB>>>(x, W1, hptr, N_NODES, F_IN);
    aggregate_kernel<<<warp_blocks, TB>>>(hptr, b1, aptr);
    // layer 2
    gemm_kernel<<<gemm_blocks, TB>>>(aptr, W2, hptr, N_NODES, F_HID);
    aggregate_kernel<<<warp_blocks, TB>>>(hptr, b2, aptr);

    // pool + fc
    pool_kernel<<<N_GRAPHS, 128>>>(aptr);
    fc_kernel<<<1, 128>>>(Wfc, bfc, out);
}

// round 3
// speedup vs baseline: 2.5891x; 1.3950x over previous
#include <cuda_runtime.h>
#include <math.h>

#define N_NODES   100000
#define N_EDGES   1600000
#define N_GRAPHS  64
#define F_IN      256
#define F_HID     128
#define NEG_SLOPE 0.01f

#define SCAN_B    1024
#define NB_SCAN   ((N_NODES + SCAN_B - 1) / SCAN_B)   // 98

// ---------------- scratch ----------------
__device__ float g_h[(size_t)N_NODES * F_HID];
__device__ float g_a[(size_t)N_NODES * F_HID];
__device__ int   g_deg[N_NODES];
__device__ int   g_fill[N_NODES];
__device__ float g_dinv[N_NODES];
__device__ int   g_rowptr[N_NODES + 1];
__device__ int   g_csrc[N_EDGES];
__device__ int   g_bsum[NB_SCAN];
__device__ int   g_boff[NB_SCAN];
__device__ int   g_gstart[N_GRAPHS + 1];
__device__ float g_pool[N_GRAPHS * F_HID];
__device__ float g_cnt[N_GRAPHS];

// ---------------- init ----------------
__global__ void zero_kernel() {
    int i = blockIdx.x * blockDim.x + threadIdx.x;
    if (i < N_NODES) { g_deg[i] = 0; g_fill[i] = 0; }
    if (i < N_GRAPHS + 1) g_gstart[i] = N_NODES;
}

// ---------------- degree ----------------
__global__ void degree_kernel(const int* __restrict__ dst) {
    int e = blockIdx.x * blockDim.x + threadIdx.x;
    if (e < N_EDGES) atomicAdd(&g_deg[dst[e]], 1);
}

__global__ void dinv_kernel() {
    int i = blockIdx.x * blockDim.x + threadIdx.x;
    if (i < N_NODES) g_dinv[i] = rsqrtf((float)g_deg[i] + 1.0f);
}

// ---------------- parallel exclusive scan: deg -> rowptr ----------------
__global__ __launch_bounds__(SCAN_B) void scan1_kernel() {
    __shared__ int red[SCAN_B];
    int t = threadIdx.x;
    int i = blockIdx.x * SCAN_B + t;
    red[t] = (i < N_NODES) ? g_deg[i] : 0;
    __syncthreads();
    for (int off = SCAN_B / 2; off > 0; off >>= 1) {
        if (t < off) red[t] += red[t + off];
        __syncthreads();
    }
    if (t == 0) g_bsum[blockIdx.x] = red[0];
}

__global__ void scan2_kernel() {
    __shared__ int s[NB_SCAN];
    int t = threadIdx.x;
    if (t < NB_SCAN) s[t] = g_bsum[t];
    __syncthreads();
    if (t == 0) {
        int run = 0;
        for (int b = 0; b < NB_SCAN; b++) { int v = s[b]; s[b] = run; run += v; }
        g_rowptr[N_NODES] = N_EDGES;
    }
    __syncthreads();
    if (t < NB_SCAN) g_boff[t] = s[t];
}

__global__ __launch_bounds__(SCAN_B) void scan3_kernel() {
    __shared__ int s[SCAN_B];
    int t = threadIdx.x;
    int i = blockIdx.x * SCAN_B + t;
    int v = (i < N_NODES) ? g_deg[i] : 0;
    s[t] = v;
    __syncthreads();
    for (int off = 1; off < SCAN_B; off <<= 1) {
        int u = (t >= off) ? s[t - off] : 0;
        __syncthreads();
        s[t] += u;
        __syncthreads();
    }
    if (i < N_NODES) g_rowptr[i] = g_boff[blockIdx.x] + s[t] - v;
}

// ---------------- CSR fill ----------------
__global__ void csr_fill_kernel(const int* __restrict__ src, const int* __restrict__ dst) {
    int e = blockIdx.x * blockDim.x + threadIdx.x;
    if (e < N_EDGES) {
        int d = dst[e];
        int pos = g_rowptr[d] + atomicAdd(&g_fill[d], 1);
        g_csrc[pos] = src[e];
    }
}

// ---------------- TF32 tensor-core GEMM: C[M,128] = A[M,K] @ B[K,128] ----------------
// BM=128, BN=128, BK=16 double-buffered. 8 warps in 2(m) x 4(n) grid,
// warp tile 64x32, mma.m16n8k8 tf32. A smem [m][k] pad 20, B smem [k][n] pad 136
// (both conflict-free for fragment loads by construction).

__device__ __forceinline__ unsigned f2tf(float x) {
    unsigned r;
    asm("cvt.rna.tf32.f32 %0, %1;" : "=r"(r) : "f"(x));
    return r;
}

__device__ __forceinline__ void mma_tf32(float* c, const unsigned* a, const unsigned* b) {
    asm volatile(
        "mma.sync.aligned.m16n8k8.row.col.f32.tf32.tf32.f32 "
        "{%0,%1,%2,%3}, {%4,%5,%6,%7}, {%8,%9}, {%0,%1,%2,%3};\n"
        : "+f"(c[0]), "+f"(c[1]), "+f"(c[2]), "+f"(c[3])
        : "r"(a[0]), "r"(a[1]), "r"(a[2]), "r"(a[3]), "r"(b[0]), "r"(b[1]));
}

#define APAD 20
#define BPAD 136

__global__ __launch_bounds__(256) void gemm_tc_kernel(
    const float* __restrict__ A, const float* __restrict__ B,
    float* __restrict__ C, int M, int K)
{
    __shared__ unsigned As[2][128][APAD];   // [m][k], BK=16 cols used
    __shared__ unsigned Bs[2][16][BPAD];    // [k][n], 128 cols used

    const int tid  = threadIdx.x;
    const int warp = tid >> 5;
    const int lane = tid & 31;
    const int g    = lane >> 2;     // 0..7
    const int t    = lane & 3;      // 0..3
    const int m0   = (warp >> 2) * 64;   // 0 or 64
    const int n0   = (warp & 3) * 32;    // 0,32,64,96
    const int block_m = blockIdx.x * 128;

    // global load mapping
    const int arow = tid >> 1;          // 0..127
    const int acol = (tid & 1) * 8;     // 0 or 8
    const int brow = tid >> 4;          // 0..15
    const int bcol = (tid & 15) * 8;    // 0..120

    const int gm_a = block_m + arow;
    const bool a_ok = (gm_a < M);
    const float* Ap = A + (size_t)gm_a * K + acol;
    const float* Bp = B + (size_t)brow * 128 + bcol;

    float acc[4][4][4];
    #pragma unroll
    for (int i = 0; i < 4; i++)
        #pragma unroll
        for (int j = 0; j < 4; j++)
            #pragma unroll
            for (int v = 0; v < 4; v++) acc[i][j][v] = 0.0f;

    // preload tile 0
    {
        float4 a0 = make_float4(0,0,0,0), a1 = make_float4(0,0,0,0);
        if (a_ok) { a0 = *(const float4*)(Ap); a1 = *(const float4*)(Ap + 4); }
        As[0][arow][acol+0] = f2tf(a0.x); As[0][arow][acol+1] = f2tf(a0.y);
        As[0][arow][acol+2] = f2tf(a0.z); As[0][arow][acol+3] = f2tf(a0.w);
        As[0][arow][acol+4] = f2tf(a1.x); As[0][arow][acol+5] = f2tf(a1.y);
        As[0][arow][acol+6] = f2tf(a1.z); As[0][arow][acol+7] = f2tf(a1.w);
        float4 b0 = *(const float4*)(Bp);
        float4 b1 = *(const float4*)(Bp + 4);
        Bs[0][brow][bcol+0] = f2tf(b0.x); Bs[0][brow][bcol+1] = f2tf(b0.y);
        Bs[0][brow][bcol+2] = f2tf(b0.z); Bs[0][brow][bcol+3] = f2tf(b0.w);
        Bs[0][brow][bcol+4] = f2tf(b1.x); Bs[0][brow][bcol+5] = f2tf(b1.y);
        Bs[0][brow][bcol+6] = f2tf(b1.z); Bs[0][brow][bcol+7] = f2tf(b1.w);
    }
    __syncthreads();

    int buf = 0;
    for (int k0 = 0; k0 < K; k0 += 16) {
        const bool more = (k0 + 16 < K);
        float4 na0, na1, nb0, nb1;
        if (more) {
            na0 = make_float4(0,0,0,0); na1 = make_float4(0,0,0,0);
            if (a_ok) {
                na0 = *(const float4*)(Ap + k0 + 16);
                na1 = *(const float4*)(Ap + k0 + 20);
            }
            nb0 = *(const float4*)(Bp + (size_t)(k0 + 16) * 128);
            nb1 = *(const float4*)(Bp + (size_t)(k0 + 16) * 128 + 4);
        }

        #pragma unroll
        for (int kk = 0; kk < 16; kk += 8) {
            unsigned bfr[4][2];
            #pragma unroll
            for (int nf = 0; nf < 4; nf++) {
                int n = n0 + nf * 8 + g;
                bfr[nf][0] = Bs[buf][kk + t][n];
                bfr[nf][1] = Bs[buf][kk + t + 4][n];
            }
            #pragma unroll
            for (int mf = 0; mf < 4; mf++) {
                int r = m0 + mf * 16 + g;
                unsigned afr[4];
                afr[0] = As[buf][r][kk + t];
                afr[1] = As[buf][r + 8][kk + t];
                afr[2] = As[buf][r][kk + t + 4];
                afr[3] = As[buf][r + 8][kk + t + 4];
                #pragma unroll
                for (int nf = 0; nf < 4; nf++)
                    mma_tf32(acc[mf][nf], afr, bfr[nf]);
            }
        }

        if (more) {
            int nb = buf ^ 1;
            As[nb][arow][acol+0] = f2tf(na0.x); As[nb][arow][acol+1] = f2tf(na0.y);
            As[nb][arow][acol+2] = f2tf(na0.z); As[nb][arow][acol+3] = f2tf(na0.w);
            As[nb][arow][acol+4] = f2tf(na1.x); As[nb][arow][acol+5] = f2tf(na1.y);
            As[nb][arow][acol+6] = f2tf(na1.z); As[nb][arow][acol+7] = f2tf(na1.w);
            Bs[nb][brow][bcol+0] = f2tf(nb0.x); Bs[nb][brow][bcol+1] = f2tf(nb0.y);
            Bs[nb][brow][bcol+2] = f2tf(nb0.z); Bs[nb][brow][bcol+3] = f2tf(nb0.w);
            Bs[nb][brow][bcol+4] = f2tf(nb1.x); Bs[nb][brow][bcol+5] = f2tf(nb1.y);
            Bs[nb][brow][bcol+6] = f2tf(nb1.z); Bs[nb][brow][bcol+7] = f2tf(nb1.w);
            __syncthreads();
            buf = nb;
        }
    }

    // epilogue
    #pragma unroll
    for (int mf = 0; mf < 4; mf++) {
        int r0 = block_m + m0 + mf * 16 + g;
        int r1 = r0 + 8;
        #pragma unroll
        for (int nf = 0; nf < 4; nf++) {
            int col = n0 + nf * 8 + t * 2;
            if (r0 < M)
                *(float2*)(C + (size_t)r0 * 128 + col) =
                    make_float2(acc[mf][nf][0], acc[mf][nf][1]);
            if (r1 < M)
                *(float2*)(C + (size_t)r1 * 128 + col) =
                    make_float2(acc[mf][nf][2], acc[mf][nf][3]);
        }
    }
}

// ---------------- aggregation: one warp per node, 4-way unrolled ----------------
__global__ __launch_bounds__(256) void aggregate_kernel(
    const float* __restrict__ h, const float* __restrict__ bias,
    float* __restrict__ out)
{
    int warp = (blockIdx.x * blockDim.x + threadIdx.x) >> 5;
    int lane = threadIdx.x & 31;
    if (warp >= N_NODES) return;
    float dv = g_dinv[warp];
    float4 hv = *(const float4*)(h + (size_t)warp * 128 + lane * 4);
    float s = dv * dv;
    float4 acc = make_float4(hv.x * s, hv.y * s, hv.z * s, hv.w * s);
    int e = g_rowptr[warp], end = g_rowptr[warp + 1];

    for (; e + 4 <= end; e += 4) {
        int s0 = g_csrc[e], s1 = g_csrc[e+1], s2 = g_csrc[e+2], s3 = g_csrc[e+3];
        float w0 = g_dinv[s0] * dv, w1 = g_dinv[s1] * dv;
        float w2 = g_dinv[s2] * dv, w3 = g_dinv[s3] * dv;
        float4 m0 = *(const float4*)(h + (size_t)s0 * 128 + lane * 4);
        float4 m1 = *(const float4*)(h + (size_t)s1 * 128 + lane * 4);
        float4 m2 = *(const float4*)(h + (size_t)s2 * 128 + lane * 4);
        float4 m3 = *(const float4*)(h + (size_t)s3 * 128 + lane * 4);
        acc.x = fmaf(m0.x, w0, acc.x); acc.y = fmaf(m0.y, w0, acc.y);
        acc.z = fmaf(m0.z, w0, acc.z); acc.w = fmaf(m0.w, w0, acc.w);
        acc.x = fmaf(m1.x, w1, acc.x); acc.y = fmaf(m1.y, w1, acc.y);
        acc.z = fmaf(m1.z, w1, acc.z); acc.w = fmaf(m1.w, w1, acc.w);
        acc.x = fmaf(m2.x, w2, acc.x); acc.y = fmaf(m2.y, w2, acc.y);
        acc.z = fmaf(m2.z, w2, acc.z); acc.w = fmaf(m2.w, w2, acc.w);
        acc.x = fmaf(m3.x, w3, acc.x); acc.y = fmaf(m3.y, w3, acc.y);
        acc.z = fmaf(m3.z, w3, acc.z); acc.w = fmaf(m3.w, w3, acc.w);
    }
    for (; e < end; e++) {
        int sv = g_csrc[e];
        float w = g_dinv[sv] * dv;
        float4 m = *(const float4*)(h + (size_t)sv * 128 + lane * 4);
        acc.x = fmaf(m.x, w, acc.x); acc.y = fmaf(m.y, w, acc.y);
        acc.z = fmaf(m.z, w, acc.z); acc.w = fmaf(m.w, w, acc.w);
    }
    float4 bv = *(const float4*)(bias + lane * 4);
    acc.x += bv.x; acc.y += bv.y; acc.z += bv.z; acc.w += bv.w;
    acc.x = acc.x > 0.f ? acc.x : NEG_SLOPE * acc.x;
    acc.y = acc.y > 0.f ? acc.y : NEG_SLOPE * acc.y;
    acc.z = acc.z > 0.f ? acc.z : NEG_SLOPE * acc.z;
    acc.w = acc.w > 0.f ? acc.w : NEG_SLOPE * acc.w;
    *(float4*)(out + (size_t)warp * 128 + lane * 4) = acc;
}

// ---------------- pool: sorted batch -> contiguous ranges ----------------
__global__ void boundary_kernel(const int* __restrict__ batch) {
    int i = blockIdx.x * blockDim.x + threadIdx.x;
    if (i < N_NODES) atomicMin(&g_gstart[batch[i]], i);
}

__global__ void boundary_fix_kernel() {
    __shared__ int s[N_GRAPHS + 1];
    int t = threadIdx.x;
    if (t < N_GRAPHS + 1) s[t] = g_gstart[t];
    __syncthreads();
    if (t == 0)
        for (int g = N_GRAPHS - 1; g >= 0; g--)
            if (s[g] > s[g + 1]) s[g] = s[g + 1];
    __syncthreads();
    if (t < N_GRAPHS + 1) g_gstart[t] = s[t];
}

__global__ __launch_bounds__(128) void pool_kernel(const float* __restrict__ act) {
    int g = blockIdx.x;
    int t = threadIdx.x;
    int beg = g_gstart[g], end = g_gstart[g + 1];
    float sum = 0.0f;
    int i = beg;
    for (; i + 4 <= end; i += 4) {
        float v0 = act[(size_t)(i+0) * 128 + t];
        float v1 = act[(size_t)(i+1) * 128 + t];
        float v2 = act[(size_t)(i+2) * 128 + t];
        float v3 = act[(size_t)(i+3) * 128 + t];
        sum += (v0 + v1) + (v2 + v3);
    }
    for (; i < end; i++) sum += act[(size_t)i * 128 + t];
    g_pool[g * 128 + t] = sum;
    if (t == 0) g_cnt[g] = (float)(end - beg);
}

// ---------------- final FC ----------------
__global__ void fc_kernel(const float* __restrict__ Wfc, const float* __restrict__ bfc,
                          float* __restrict__ out)
{
    int t = threadIdx.x;
    if (t >= N_GRAPHS * 2) return;
    int g = t >> 1, c = t & 1;
    float inv = 1.0f / fmaxf(g_cnt[g], 1.0f);
    float sum = 0.0f;
    #pragma unroll 4
    for (int k = 0; k < 128; k++)
        sum = fmaf(g_pool[g * 128 + k] * inv, Wfc[k * 2 + c], sum);
    out[t] = sum + bfc[c];
}

// ---------------- launch ----------------
extern "C" void kernel_launch(void* const* d_in, const int* in_sizes, int n_in,
                              void* d_out, int out_size)
{
    const float* x   = (const float*)d_in[0];
    const int*   ei  = (const int*)d_in[1];
    const int*   bat = (const int*)d_in[2];
    const float* W1  = (const float*)d_in[3];
    const float* b1  = (const float*)d_in[4];
    const float* W2  = (const float*)d_in[5];
    const float* b2  = (const float*)d_in[6];
    const float* Wfc = (const float*)d_in[7];
    const float* bfc = (const float*)d_in[8];
    float* out = (float*)d_out;
    const int* src = ei;
    const int* dst = ei + N_EDGES;

    float *hptr, *aptr;
    cudaGetSymbolAddress((void**)&hptr, g_h);
    cudaGetSymbolAddress((void**)&aptr, g_a);

    const int TB = 256;
    int node_blocks = (N_NODES + TB - 1) / TB;
    int edge_blocks = (N_EDGES + TB - 1) / TB;
    int warp_blocks = (N_NODES * 32 + TB - 1) / TB;
    int gemm_blocks = (N_NODES + 127) / 128;

    zero_kernel<<<node_blocks, TB>>>();
    degree_kernel<<<edge_blocks, TB>>>(dst);
    dinv_kernel<<<node_blocks, TB>>>();
    scan1_kernel<<<NB_SCAN, SCAN_B>>>();
    scan2_kernel<<<1, 128>>>();
    scan3_kernel<<<NB_SCAN, SCAN_B>>>();
    csr_fill_kernel<<<edge_blocks, TB>>>(src, dst);
    boundary_kernel<<<node_blocks, TB>>>(bat);
    boundary_fix_kernel<<<1, 128>>>();

    // layer 1
    gemm_tc_kernel<<<gemm_blocks, TB>>>(x, W1, hptr, N_NODES, F_IN);
    aggregate_kernel<<<warp_blocks, TB>>>(hptr, b1, aptr);
    // layer 2
    gemm_tc_kernel<<<gemm_blocks, TB>>>(aptr, W2, hptr, N_NODES, F_HID);
    aggregate_kernel<<<warp_blocks, TB>>>(hptr, b2, aptr);

    // pool + fc
    pool_kernel<<<N_GRAPHS, 128>>>(aptr);
    fc_kernel<<<1, 128>>>(Wfc, bfc, out);
}

// round 4
// speedup vs baseline: 2.7375x; 1.0573x over previous
#include <cuda_runtime.h>
#include <cuda_fp16.h>
#include <math.h>

#define N_NODES   100000
#define N_EDGES   1600000
#define N_GRAPHS  64
#define F_IN      256
#define F_HID     128
#define NEG_SLOPE 0.01f

#define SCAN_B    1024
#define NB_SCAN   ((N_NODES + SCAN_B - 1) / SCAN_B)   // 98

// ---------------- scratch ----------------
__device__ __half g_h[(size_t)N_NODES * F_HID];   // GEMM output (fp16, gather source)
__device__ float  g_a[(size_t)N_NODES * F_HID];   // aggregate output (fp32)
__device__ int    g_deg[N_NODES];
__device__ int    g_fill[N_NODES];
__device__ float  g_dinv[N_NODES];
__device__ int    g_rowptr[N_NODES + 1];
__device__ int    g_csrc[N_EDGES];
__device__ int    g_bsum[NB_SCAN];
__device__ int    g_boff[NB_SCAN];
__device__ int    g_gstart[N_GRAPHS + 1];
__device__ float  g_pool[N_GRAPHS * F_HID];
__device__ float  g_cnt[N_GRAPHS];

// ---------------- init ----------------
__global__ void zero_kernel() {
    int i = blockIdx.x * blockDim.x + threadIdx.x;
    if (i < N_NODES) { g_deg[i] = 0; g_fill[i] = 0; }
    if (i < N_GRAPHS + 1) g_gstart[i] = N_NODES;
}

// ---------------- degree ----------------
__global__ void degree_kernel(const int* __restrict__ dst) {
    int e = blockIdx.x * blockDim.x + threadIdx.x;
    if (e < N_EDGES) atomicAdd(&g_deg[dst[e]], 1);
}

__global__ void dinv_kernel() {
    int i = blockIdx.x * blockDim.x + threadIdx.x;
    if (i < N_NODES) g_dinv[i] = rsqrtf((float)g_deg[i] + 1.0f);
}

// ---------------- parallel exclusive scan: deg -> rowptr ----------------
__global__ __launch_bounds__(SCAN_B) void scan1_kernel() {
    __shared__ int red[SCAN_B];
    int t = threadIdx.x;
    int i = blockIdx.x * SCAN_B + t;
    red[t] = (i < N_NODES) ? g_deg[i] : 0;
    __syncthreads();
    for (int off = SCAN_B / 2; off > 0; off >>= 1) {
        if (t < off) red[t] += red[t + off];
        __syncthreads();
    }
    if (t == 0) g_bsum[blockIdx.x] = red[0];
}

__global__ void scan2_kernel() {
    __shared__ int s[NB_SCAN];
    int t = threadIdx.x;
    if (t < NB_SCAN) s[t] = g_bsum[t];
    __syncthreads();
    if (t == 0) {
        int run = 0;
        for (int b = 0; b < NB_SCAN; b++) { int v = s[b]; s[b] = run; run += v; }
        g_rowptr[N_NODES] = N_EDGES;
    }
    __syncthreads();
    if (t < NB_SCAN) g_boff[t] = s[t];
}

__global__ __launch_bounds__(SCAN_B) void scan3_kernel() {
    __shared__ int s[SCAN_B];
    int t = threadIdx.x;
    int i = blockIdx.x * SCAN_B + t;
    int v = (i < N_NODES) ? g_deg[i] : 0;
    s[t] = v;
    __syncthreads();
    for (int off = 1; off < SCAN_B; off <<= 1) {
        int u = (t >= off) ? s[t - off] : 0;
        __syncthreads();
        s[t] += u;
        __syncthreads();
    }
    if (i < N_NODES) g_rowptr[i] = g_boff[blockIdx.x] + s[t] - v;
}

// ---------------- CSR fill ----------------
__global__ void csr_fill_kernel(const int* __restrict__ src, const int* __restrict__ dst) {
    int e = blockIdx.x * blockDim.x + threadIdx.x;
    if (e < N_EDGES) {
        int d = dst[e];
        int pos = g_rowptr[d] + atomicAdd(&g_fill[d], 1);
        g_csrc[pos] = src[e];
    }
}

// ---------------- TF32 tensor-core GEMM: C[M,128] = A[M,K] @ B[K,128], C fp16 ----------------
__device__ __forceinline__ unsigned f2tf(float x) {
    unsigned r;
    asm("cvt.rna.tf32.f32 %0, %1;" : "=r"(r) : "f"(x));
    return r;
}

__device__ __forceinline__ void mma_tf32(float* c, const unsigned* a, const unsigned* b) {
    asm volatile(
        "mma.sync.aligned.m16n8k8.row.col.f32.tf32.tf32.f32 "
        "{%0,%1,%2,%3}, {%4,%5,%6,%7}, {%8,%9}, {%0,%1,%2,%3};\n"
        : "+f"(c[0]), "+f"(c[1]), "+f"(c[2]), "+f"(c[3])
        : "r"(a[0]), "r"(a[1]), "r"(a[2]), "r"(a[3]), "r"(b[0]), "r"(b[1]));
}

#define APAD 20
#define BPAD 136

__global__ __launch_bounds__(256) void gemm_tc_kernel(
    const float* __restrict__ A, const float* __restrict__ B,
    __half* __restrict__ C, int M, int K)
{
    __shared__ unsigned As[2][128][APAD];   // [m][k], BK=16 cols used
    __shared__ unsigned Bs[2][16][BPAD];    // [k][n], 128 cols used

    const int tid  = threadIdx.x;
    const int warp = tid >> 5;
    const int lane = tid & 31;
    const int g    = lane >> 2;     // 0..7
    const int t    = lane & 3;      // 0..3
    const int m0   = (warp >> 2) * 64;
    const int n0   = (warp & 3) * 32;
    const int block_m = blockIdx.x * 128;

    const int arow = tid >> 1;
    const int acol = (tid & 1) * 8;
    const int brow = tid >> 4;
    const int bcol = (tid & 15) * 8;

    const int gm_a = block_m + arow;
    const bool a_ok = (gm_a < M);
    const float* Ap = A + (size_t)gm_a * K + acol;
    const float* Bp = B + (size_t)brow * 128 + bcol;

    float acc[4][4][4];
    #pragma unroll
    for (int i = 0; i < 4; i++)
        #pragma unroll
        for (int j = 0; j < 4; j++)
            #pragma unroll
            for (int v = 0; v < 4; v++) acc[i][j][v] = 0.0f;

    {
        float4 a0 = make_float4(0,0,0,0), a1 = make_float4(0,0,0,0);
        if (a_ok) { a0 = *(const float4*)(Ap); a1 = *(const float4*)(Ap + 4); }
        As[0][arow][acol+0] = f2tf(a0.x); As[0][arow][acol+1] = f2tf(a0.y);
        As[0][arow][acol+2] = f2tf(a0.z); As[0][arow][acol+3] = f2tf(a0.w);
        As[0][arow][acol+4] = f2tf(a1.x); As[0][arow][acol+5] = f2tf(a1.y);
        As[0][arow][acol+6] = f2tf(a1.z); As[0][arow][acol+7] = f2tf(a1.w);
        float4 b0 = *(const float4*)(Bp);
        float4 b1 = *(const float4*)(Bp + 4);
        Bs[0][brow][bcol+0] = f2tf(b0.x); Bs[0][brow][bcol+1] = f2tf(b0.y);
        Bs[0][brow][bcol+2] = f2tf(b0.z); Bs[0][brow][bcol+3] = f2tf(b0.w);
        Bs[0][brow][bcol+4] = f2tf(b1.x); Bs[0][brow][bcol+5] = f2tf(b1.y);
        Bs[0][brow][bcol+6] = f2tf(b1.z); Bs[0][brow][bcol+7] = f2tf(b1.w);
    }
    __syncthreads();

    int buf = 0;
    for (int k0 = 0; k0 < K; k0 += 16) {
        const bool more = (k0 + 16 < K);
        float4 na0, na1, nb0, nb1;
        if (more) {
            na0 = make_float4(0,0,0,0); na1 = make_float4(0,0,0,0);
            if (a_ok) {
                na0 = *(const float4*)(Ap + k0 + 16);
                na1 = *(const float4*)(Ap + k0 + 20);
            }
            nb0 = *(const float4*)(Bp + (size_t)(k0 + 16) * 128);
            nb1 = *(const float4*)(Bp + (size_t)(k0 + 16) * 128 + 4);
        }

        #pragma unroll
        for (int kk = 0; kk < 16; kk += 8) {
            unsigned bfr[4][2];
            #pragma unroll
            for (int nf = 0; nf < 4; nf++) {
                int n = n0 + nf * 8 + g;
                bfr[nf][0] = Bs[buf][kk + t][n];
                bfr[nf][1] = Bs[buf][kk + t + 4][n];
            }
            #pragma unroll
            for (int mf = 0; mf < 4; mf++) {
                int r = m0 + mf * 16 + g;
                unsigned afr[4];
                afr[0] = As[buf][r][kk + t];
                afr[1] = As[buf][r + 8][kk + t];
                afr[2] = As[buf][r][kk + t + 4];
                afr[3] = As[buf][r + 8][kk + t + 4];
                #pragma unroll
                for (int nf = 0; nf < 4; nf++)
                    mma_tf32(acc[mf][nf], afr, bfr[nf]);
            }
        }

        if (more) {
            int nb = buf ^ 1;
            As[nb][arow][acol+0] = f2tf(na0.x); As[nb][arow][acol+1] = f2tf(na0.y);
            As[nb][arow][acol+2] = f2tf(na0.z); As[nb][arow][acol+3] = f2tf(na0.w);
            As[nb][arow][acol+4] = f2tf(na1.x); As[nb][arow][acol+5] = f2tf(na1.y);
            As[nb][arow][acol+6] = f2tf(na1.z); As[nb][arow][acol+7] = f2tf(na1.w);
            Bs[nb][brow][bcol+0] = f2tf(nb0.x); Bs[nb][brow][bcol+1] = f2tf(nb0.y);
            Bs[nb][brow][bcol+2] = f2tf(nb0.z); Bs[nb][brow][bcol+3] = f2tf(nb0.w);
            Bs[nb][brow][bcol+4] = f2tf(nb1.x); Bs[nb][brow][bcol+5] = f2tf(nb1.y);
            Bs[nb][brow][bcol+6] = f2tf(nb1.z); Bs[nb][brow][bcol+7] = f2tf(nb1.w);
            __syncthreads();
            buf = nb;
        }
    }

    // epilogue: fp16 stores
    #pragma unroll
    for (int mf = 0; mf < 4; mf++) {
        int r0 = block_m + m0 + mf * 16 + g;
        int r1 = r0 + 8;
        #pragma unroll
        for (int nf = 0; nf < 4; nf++) {
            int col = n0 + nf * 8 + t * 2;
            if (r0 < M)
                *(__half2*)(C + (size_t)r0 * 128 + col) =
                    __floats2half2_rn(acc[mf][nf][0], acc[mf][nf][1]);
            if (r1 < M)
                *(__half2*)(C + (size_t)r1 * 128 + col) =
                    __floats2half2_rn(acc[mf][nf][2], acc[mf][nf][3]);
        }
    }
}

// ---------------- aggregation: one warp per node, fp16 gather, fp32 accumulate ----------------
__device__ __forceinline__ void acc_row(float4& acc, const __half* __restrict__ h,
                                        int src, int lane, float w)
{
    uint2 raw = *(const uint2*)(h + (size_t)src * 128 + lane * 4);
    __half2 p0 = *reinterpret_cast<__half2*>(&raw.x);
    __half2 p1 = *reinterpret_cast<__half2*>(&raw.y);
    float2 f0 = __half22float2(p0);
    float2 f1 = __half22float2(p1);
    acc.x = fmaf(f0.x, w, acc.x);
    acc.y = fmaf(f0.y, w, acc.y);
    acc.z = fmaf(f1.x, w, acc.z);
    acc.w = fmaf(f1.y, w, acc.w);
}

__global__ __launch_bounds__(256) void aggregate_kernel(
    const __half* __restrict__ h, const float* __restrict__ bias,
    float* __restrict__ out)
{
    int warp = (blockIdx.x * blockDim.x + threadIdx.x) >> 5;
    int lane = threadIdx.x & 31;
    if (warp >= N_NODES) return;
    float dv = g_dinv[warp];
    float4 acc = make_float4(0.f, 0.f, 0.f, 0.f);
    acc_row(acc, h, warp, lane, dv * dv);   // self-loop
    int e = g_rowptr[warp], end = g_rowptr[warp + 1];

    for (; e + 4 <= end; e += 4) {
        int s0 = g_csrc[e], s1 = g_csrc[e+1], s2 = g_csrc[e+2], s3 = g_csrc[e+3];
        float w0 = g_dinv[s0] * dv, w1 = g_dinv[s1] * dv;
        float w2 = g_dinv[s2] * dv, w3 = g_dinv[s3] * dv;
        uint2 r0 = *(const uint2*)(h + (size_t)s0 * 128 + lane * 4);
        uint2 r1 = *(const uint2*)(h + (size_t)s1 * 128 + lane * 4);
        uint2 r2 = *(const uint2*)(h + (size_t)s2 * 128 + lane * 4);
        uint2 r3 = *(const uint2*)(h + (size_t)s3 * 128 + lane * 4);
        float2 a0 = __half22float2(*reinterpret_cast<__half2*>(&r0.x));
        float2 b0 = __half22float2(*reinterpret_cast<__half2*>(&r0.y));
        float2 a1 = __half22float2(*reinterpret_cast<__half2*>(&r1.x));
        float2 b1 = __half22float2(*reinterpret_cast<__half2*>(&r1.y));
        float2 a2 = __half22float2(*reinterpret_cast<__half2*>(&r2.x));
        float2 b2 = __half22float2(*reinterpret_cast<__half2*>(&r2.y));
        float2 a3 = __half22float2(*reinterpret_cast<__half2*>(&r3.x));
        float2 b3 = __half22float2(*reinterpret_cast<__half2*>(&r3.y));
        acc.x = fmaf(a0.x, w0, acc.x); acc.y = fmaf(a0.y, w0, acc.y);
        acc.z = fmaf(b0.x, w0, acc.z); acc.w = fmaf(b0.y, w0, acc.w);
        acc.x = fmaf(a1.x, w1, acc.x); acc.y = fmaf(a1.y, w1, acc.y);
        acc.z = fmaf(b1.x, w1, acc.z); acc.w = fmaf(b1.y, w1, acc.w);
        acc.x = fmaf(a2.x, w2, acc.x); acc.y = fmaf(a2.y, w2, acc.y);
        acc.z = fmaf(b2.x, w2, acc.z); acc.w = fmaf(b2.y, w2, acc.w);
        acc.x = fmaf(a3.x, w3, acc.x); acc.y = fmaf(a3.y, w3, acc.y);
        acc.z = fmaf(b3.x, w3, acc.z); acc.w = fmaf(b3.y, w3, acc.w);
    }
    for (; e < end; e++) {
        int sv = g_csrc[e];
        acc_row(acc, h, sv, lane, g_dinv[sv] * dv);
    }
    float4 bv = *(const float4*)(bias + lane * 4);
    acc.x += bv.x; acc.y += bv.y; acc.z += bv.z; acc.w += bv.w;
    acc.x = acc.x > 0.f ? acc.x : NEG_SLOPE * acc.x;
    acc.y = acc.y > 0.f ? acc.y : NEG_SLOPE * acc.y;
    acc.z = acc.z > 0.f ? acc.z : NEG_SLOPE * acc.z;
    acc.w = acc.w > 0.f ? acc.w : NEG_SLOPE * acc.w;
    *(float4*)(out + (size_t)warp * 128 + lane * 4) = acc;
}

// ---------------- pool: sorted batch -> contiguous ranges ----------------
__global__ void boundary_kernel(const int* __restrict__ batch) {
    int i = blockIdx.x * blockDim.x + threadIdx.x;
    if (i < N_NODES) atomicMin(&g_gstart[batch[i]], i);
}

__global__ void boundary_fix_kernel() {
    __shared__ int s[N_GRAPHS + 1];
    int t = threadIdx.x;
    if (t < N_GRAPHS + 1) s[t] = g_gstart[t];
    __syncthreads();
    if (t == 0)
        for (int g = N_GRAPHS - 1; g >= 0; g--)
            if (s[g] > s[g + 1]) s[g] = s[g + 1];
    __syncthreads();
    if (t < N_GRAPHS + 1) g_gstart[t] = s[t];
}

__global__ __launch_bounds__(128) void pool_kernel(const float* __restrict__ act) {
    int g = blockIdx.x;
    int t = threadIdx.x;
    int beg = g_gstart[g], end = g_gstart[g + 1];
    float sum = 0.0f;
    int i = beg;
    for (; i + 4 <= end; i += 4) {
        float v0 = act[(size_t)(i+0) * 128 + t];
        float v1 = act[(size_t)(i+1) * 128 + t];
        float v2 = act[(size_t)(i+2) * 128 + t];
        float v3 = act[(size_t)(i+3) * 128 + t];
        sum += (v0 + v1) + (v2 + v3);
    }
    for (; i < end; i++) sum += act[(size_t)i * 128 + t];
    g_pool[g * 128 + t] = sum;
    if (t == 0) g_cnt[g] = (float)(end - beg);
}

// ---------------- final FC ----------------
__global__ void fc_kernel(const float* __restrict__ Wfc, const float* __restrict__ bfc,
                          float* __restrict__ out)
{
    int t = threadIdx.x;
    if (t >= N_GRAPHS * 2) return;
    int g = t >> 1, c = t & 1;
    float inv = 1.0f / fmaxf(g_cnt[g], 1.0f);
    float sum = 0.0f;
    #pragma unroll 4
    for (int k = 0; k < 128; k++)
        sum = fmaf(g_pool[g * 128 + k] * inv, Wfc[k * 2 + c], sum);
    out[t] = sum + bfc[c];
}

// ---------------- launch ----------------
extern "C" void kernel_launch(void* const* d_in, const int* in_sizes, int n_in,
                              void* d_out, int out_size)
{
    const float* x   = (const float*)d_in[0];
    const int*   ei  = (const int*)d_in[1];
    const int*   bat = (const int*)d_in[2];
    const float* W1  = (const float*)d_in[3];
    const float* b1  = (const float*)d_in[4];
    const float* W2  = (const float*)d_in[5];
    const float* b2  = (const float*)d_in[6];
    const float* Wfc = (const float*)d_in[7];
    const float* bfc = (const float*)d_in[8];
    float* out = (float*)d_out;
    const int* src = ei;
    const int* dst = ei + N_EDGES;

    __half* hptr;
    float*  aptr;
    cudaGetSymbolAddress((void**)&hptr, g_h);
    cudaGetSymbolAddress((void**)&aptr, g_a);

    const int TB = 256;
    int node_blocks = (N_NODES + TB - 1) / TB;
    int edge_blocks = (N_EDGES + TB - 1) / TB;
    int warp_blocks = (N_NODES * 32 + TB - 1) / TB;
    int gemm_blocks = (N_NODES + 127) / 128;

    zero_kernel<<<node_blocks, TB>>>();
    degree_kernel<<<edge_blocks, TB>>>(dst);
    dinv_kernel<<<node_blocks, TB>>>();
    scan1_kernel<<<NB_SCAN, SCAN_B>>>();
    scan2_kernel<<<1, 128>>>();
    scan3_kernel<<<NB_SCAN, SCAN_B>>>();
    csr_fill_kernel<<<edge_blocks, TB>>>(src, dst);
    boundary_kernel<<<node_blocks, TB>>>(bat);
    boundary_fix_kernel<<<1, 128>>>();

    // layer 1
    gemm_tc_kernel<<<gemm_blocks, TB>>>(x, W1, hptr, N_NODES, F_IN);
    aggregate_kernel<<<warp_blocks, TB>>>(hptr, b1, aptr);
    // layer 2
    gemm_tc_kernel<<<gemm_blocks, TB>>>(aptr, W2, hptr, N_NODES, F_HID);
    aggregate_kernel<<<warp_blocks, TB>>>(hptr, b2, aptr);

    // pool + fc
    pool_kernel<<<N_GRAPHS, 128>>>(aptr);
    fc_kernel<<<1, 128>>>(Wfc, bfc, out);
}

// round 5
// speedup vs baseline: 3.4990x; 1.2782x over previous
#include <cuda_runtime.h>
#include <cuda_fp16.h>
#include <math.h>

#define N_NODES   100000
#define N_EDGES   1600000
#define N_GRAPHS  64
#define F_IN      256
#define F_HID     128
#define NEG_SLOPE 0.01f

#define SCAN_B    1024
#define NB_SCAN   ((N_NODES + SCAN_B - 1) / SCAN_B)   // 98

// ---------------- scratch ----------------
__device__ __half g_h[(size_t)N_NODES * F_HID];   // GEMM output (fp16)
__device__ __half g_a[(size_t)N_NODES * F_HID];   // aggregate output (fp16)
__device__ int    g_deg[N_NODES];
__device__ int    g_fill[N_NODES];
__device__ float  g_dinv[N_NODES];
__device__ int    g_rowptr[N_NODES + 1];
__device__ int    g_csrc[N_EDGES];
__device__ int    g_bsum[NB_SCAN];
__device__ int    g_boff[NB_SCAN];
__device__ float  g_pool[N_GRAPHS * F_HID];
__device__ float  g_cnt[N_GRAPHS];

// ---------------- init ----------------
__global__ void zero_kernel() {
    int i = blockIdx.x * blockDim.x + threadIdx.x;
    if (i < N_NODES) { g_deg[i] = 0; g_fill[i] = 0; }
}

// ---------------- degree ----------------
__global__ void degree_kernel(const int* __restrict__ dst) {
    int e = blockIdx.x * blockDim.x + threadIdx.x;
    if (e < N_EDGES) atomicAdd(&g_deg[dst[e]], 1);
}

__global__ void dinv_kernel() {
    int i = blockIdx.x * blockDim.x + threadIdx.x;
    if (i < N_NODES) g_dinv[i] = rsqrtf((float)g_deg[i] + 1.0f);
}

// ---------------- parallel exclusive scan: deg -> rowptr ----------------
__global__ __launch_bounds__(SCAN_B) void scan1_kernel() {
    __shared__ int red[SCAN_B];
    int t = threadIdx.x;
    int i = blockIdx.x * SCAN_B + t;
    red[t] = (i < N_NODES) ? g_deg[i] : 0;
    __syncthreads();
    for (int off = SCAN_B / 2; off > 0; off >>= 1) {
        if (t < off) red[t] += red[t + off];
        __syncthreads();
    }
    if (t == 0) g_bsum[blockIdx.x] = red[0];
}

__global__ void scan2_kernel() {
    __shared__ int s[NB_SCAN];
    int t = threadIdx.x;
    if (t < NB_SCAN) s[t] = g_bsum[t];
    __syncthreads();
    if (t == 0) {
        int run = 0;
        for (int b = 0; b < NB_SCAN; b++) { int v = s[b]; s[b] = run; run += v; }
        g_rowptr[N_NODES] = N_EDGES;
    }
    __syncthreads();
    if (t < NB_SCAN) g_boff[t] = s[t];
}

__global__ __launch_bounds__(SCAN_B) void scan3_kernel() {
    __shared__ int s[SCAN_B];
    int t = threadIdx.x;
    int i = blockIdx.x * SCAN_B + t;
    int v = (i < N_NODES) ? g_deg[i] : 0;
    s[t] = v;
    __syncthreads();
    for (int off = 1; off < SCAN_B; off <<= 1) {
        int u = (t >= off) ? s[t - off] : 0;
        __syncthreads();
        s[t] += u;
        __syncthreads();
    }
    if (i < N_NODES) g_rowptr[i] = g_boff[blockIdx.x] + s[t] - v;
}

// ---------------- CSR fill ----------------
__global__ void csr_fill_kernel(const int* __restrict__ src, const int* __restrict__ dst) {
    int e = blockIdx.x * blockDim.x + threadIdx.x;
    if (e < N_EDGES) {
        int d = dst[e];
        int pos = g_rowptr[d] + atomicAdd(&g_fill[d], 1);
        g_csrc[pos] = src[e];
    }
}

// ---------------- TF32 tensor-core GEMM (templated A dtype) ----------------
__device__ __forceinline__ unsigned f2tf(float x) {
    unsigned r;
    asm("cvt.rna.tf32.f32 %0, %1;" : "=r"(r) : "f"(x));
    return r;
}

__device__ __forceinline__ void mma_tf32(float* c, const unsigned* a, const unsigned* b) {
    asm volatile(
        "mma.sync.aligned.m16n8k8.row.col.f32.tf32.tf32.f32 "
        "{%0,%1,%2,%3}, {%4,%5,%6,%7}, {%8,%9}, {%0,%1,%2,%3};\n"
        : "+f"(c[0]), "+f"(c[1]), "+f"(c[2]), "+f"(c[3])
        : "r"(a[0]), "r"(a[1]), "r"(a[2]), "r"(a[3]), "r"(b[0]), "r"(b[1]));
}

__device__ __forceinline__ void load_a8(const float* p, bool ok, unsigned v[8]) {
    float4 a0 = make_float4(0,0,0,0), a1 = make_float4(0,0,0,0);
    if (ok) { a0 = *(const float4*)p; a1 = *(const float4*)(p + 4); }
    v[0]=f2tf(a0.x); v[1]=f2tf(a0.y); v[2]=f2tf(a0.z); v[3]=f2tf(a0.w);
    v[4]=f2tf(a1.x); v[5]=f2tf(a1.y); v[6]=f2tf(a1.z); v[7]=f2tf(a1.w);
}

__device__ __forceinline__ void load_a8(const __half* p, bool ok, unsigned v[8]) {
    uint4 raw = make_uint4(0,0,0,0);
    if (ok) raw = *(const uint4*)p;
    float2 f0 = __half22float2(*reinterpret_cast<__half2*>(&raw.x));
    float2 f1 = __half22float2(*reinterpret_cast<__half2*>(&raw.y));
    float2 f2_ = __half22float2(*reinterpret_cast<__half2*>(&raw.z));
    float2 f3 = __half22float2(*reinterpret_cast<__half2*>(&raw.w));
    v[0]=f2tf(f0.x); v[1]=f2tf(f0.y); v[2]=f2tf(f1.x); v[3]=f2tf(f1.y);
    v[4]=f2tf(f2_.x); v[5]=f2tf(f2_.y); v[6]=f2tf(f3.x); v[7]=f2tf(f3.y);
}

#define APAD 20
#define BPAD 136

template <typename TA>
__global__ __launch_bounds__(256) void gemm_tc_kernel(
    const TA* __restrict__ A, const float* __restrict__ B,
    __half* __restrict__ C, int M, int K)
{
    __shared__ unsigned As[2][128][APAD];   // [m][k], BK=16 cols used
    __shared__ unsigned Bs[2][16][BPAD];    // [k][n], 128 cols used

    const int tid  = threadIdx.x;
    const int warp = tid >> 5;
    const int lane = tid & 31;
    const int g    = lane >> 2;
    const int t    = lane & 3;
    const int m0   = (warp >> 2) * 64;
    const int n0   = (warp & 3) * 32;
    const int block_m = blockIdx.x * 128;

    const int arow = tid >> 1;
    const int acol = (tid & 1) * 8;
    const int brow = tid >> 4;
    const int bcol = (tid & 15) * 8;

    const int gm_a = block_m + arow;
    const bool a_ok = (gm_a < M);
    const TA* Ap = A + (size_t)gm_a * K + acol;
    const float* Bp = B + (size_t)brow * 128 + bcol;

    float acc[4][4][4];
    #pragma unroll
    for (int i = 0; i < 4; i++)
        #pragma unroll
        for (int j = 0; j < 4; j++)
            #pragma unroll
            for (int v = 0; v < 4; v++) acc[i][j][v] = 0.0f;

    {
        unsigned av[8];
        load_a8(Ap, a_ok, av);
        #pragma unroll
        for (int q = 0; q < 8; q++) As[0][arow][acol + q] = av[q];
        float4 b0 = *(const float4*)(Bp);
        float4 b1 = *(const float4*)(Bp + 4);
        Bs[0][brow][bcol+0] = f2tf(b0.x); Bs[0][brow][bcol+1] = f2tf(b0.y);
        Bs[0][brow][bcol+2] = f2tf(b0.z); Bs[0][brow][bcol+3] = f2tf(b0.w);
        Bs[0][brow][bcol+4] = f2tf(b1.x); Bs[0][brow][bcol+5] = f2tf(b1.y);
        Bs[0][brow][bcol+6] = f2tf(b1.z); Bs[0][brow][bcol+7] = f2tf(b1.w);
    }
    __syncthreads();

    int buf = 0;
    for (int k0 = 0; k0 < K; k0 += 16) {
        const bool more = (k0 + 16 < K);
        unsigned av[8];
        float4 nb0, nb1;
        if (more) {
            load_a8(Ap + k0 + 16, a_ok, av);
            nb0 = *(const float4*)(Bp + (size_t)(k0 + 16) * 128);
            nb1 = *(const float4*)(Bp + (size_t)(k0 + 16) * 128 + 4);
        }

        #pragma unroll
        for (int kk = 0; kk < 16; kk += 8) {
            unsigned bfr[4][2];
            #pragma unroll
            for (int nf = 0; nf < 4; nf++) {
                int n = n0 + nf * 8 + g;
                bfr[nf][0] = Bs[buf][kk + t][n];
                bfr[nf][1] = Bs[buf][kk + t + 4][n];
            }
            #pragma unroll
            for (int mf = 0; mf < 4; mf++) {
                int r = m0 + mf * 16 + g;
                unsigned afr[4];
                afr[0] = As[buf][r][kk + t];
                afr[1] = As[buf][r + 8][kk + t];
                afr[2] = As[buf][r][kk + t + 4];
                afr[3] = As[buf][r + 8][kk + t + 4];
                #pragma unroll
                for (int nf = 0; nf < 4; nf++)
                    mma_tf32(acc[mf][nf], afr, bfr[nf]);
            }
        }

        if (more) {
            int nb = buf ^ 1;
            #pragma unroll
            for (int q = 0; q < 8; q++) As[nb][arow][acol + q] = av[q];
            Bs[nb][brow][bcol+0] = f2tf(nb0.x); Bs[nb][brow][bcol+1] = f2tf(nb0.y);
            Bs[nb][brow][bcol+2] = f2tf(nb0.z); Bs[nb][brow][bcol+3] = f2tf(nb0.w);
            Bs[nb][brow][bcol+4] = f2tf(nb1.x); Bs[nb][brow][bcol+5] = f2tf(nb1.y);
            Bs[nb][brow][bcol+6] = f2tf(nb1.z); Bs[nb][brow][bcol+7] = f2tf(nb1.w);
            __syncthreads();
            buf = nb;
        }
    }

    #pragma unroll
    for (int mf = 0; mf < 4; mf++) {
        int r0 = block_m + m0 + mf * 16 + g;
        int r1 = r0 + 8;
        #pragma unroll
        for (int nf = 0; nf < 4; nf++) {
            int col = n0 + nf * 8 + t * 2;
            if (r0 < M)
                *(__half2*)(C + (size_t)r0 * 128 + col) =
                    __floats2half2_rn(acc[mf][nf][0], acc[mf][nf][1]);
            if (r1 < M)
                *(__half2*)(C + (size_t)r1 * 128 + col) =
                    __floats2half2_rn(acc[mf][nf][2], acc[mf][nf][3]);
        }
    }
}

// ---------------- aggregation: warp/node, fp16 gather, unroll 8, fp16 out ----------------
#define ACC1(R, W)                                                           \
    {                                                                        \
        float2 _a = __half22float2(*reinterpret_cast<__half2*>(&(R).x));     \
        float2 _b = __half22float2(*reinterpret_cast<__half2*>(&(R).y));     \
        acc.x = fmaf(_a.x, (W), acc.x); acc.y = fmaf(_a.y, (W), acc.y);      \
        acc.z = fmaf(_b.x, (W), acc.z); acc.w = fmaf(_b.y, (W), acc.w);      \
    }

__global__ __launch_bounds__(256) void aggregate_kernel(
    const __half* __restrict__ h, const float* __restrict__ bias,
    __half* __restrict__ out)
{
    int warp = (blockIdx.x * blockDim.x + threadIdx.x) >> 5;
    int lane = threadIdx.x & 31;
    if (warp >= N_NODES) return;
    float dv = g_dinv[warp];
    float4 acc = make_float4(0.f, 0.f, 0.f, 0.f);
    {   // self loop
        uint2 r = *(const uint2*)(h + (size_t)warp * 128 + lane * 4);
        float w = dv * dv;
        ACC1(r, w);
    }
    int e = g_rowptr[warp], end = g_rowptr[warp + 1];

    for (; e + 8 <= end; e += 8) {
        int s0 = g_csrc[e+0], s1 = g_csrc[e+1], s2 = g_csrc[e+2], s3 = g_csrc[e+3];
        int s4 = g_csrc[e+4], s5 = g_csrc[e+5], s6 = g_csrc[e+6], s7 = g_csrc[e+7];
        uint2 r0 = *(const uint2*)(h + (size_t)s0 * 128 + lane * 4);
        uint2 r1 = *(const uint2*)(h + (size_t)s1 * 128 + lane * 4);
        uint2 r2 = *(const uint2*)(h + (size_t)s2 * 128 + lane * 4);
        uint2 r3 = *(const uint2*)(h + (size_t)s3 * 128 + lane * 4);
        uint2 r4 = *(const uint2*)(h + (size_t)s4 * 128 + lane * 4);
        uint2 r5 = *(const uint2*)(h + (size_t)s5 * 128 + lane * 4);
        uint2 r6 = *(const uint2*)(h + (size_t)s6 * 128 + lane * 4);
        uint2 r7 = *(const uint2*)(h + (size_t)s7 * 128 + lane * 4);
        float w0 = g_dinv[s0] * dv, w1 = g_dinv[s1] * dv;
        float w2 = g_dinv[s2] * dv, w3 = g_dinv[s3] * dv;
        float w4 = g_dinv[s4] * dv, w5 = g_dinv[s5] * dv;
        float w6 = g_dinv[s6] * dv, w7 = g_dinv[s7] * dv;
        ACC1(r0, w0); ACC1(r1, w1); ACC1(r2, w2); ACC1(r3, w3);
        ACC1(r4, w4); ACC1(r5, w5); ACC1(r6, w6); ACC1(r7, w7);
    }
    for (; e + 4 <= end; e += 4) {
        int s0 = g_csrc[e+0], s1 = g_csrc[e+1], s2 = g_csrc[e+2], s3 = g_csrc[e+3];
        uint2 r0 = *(const uint2*)(h + (size_t)s0 * 128 + lane * 4);
        uint2 r1 = *(const uint2*)(h + (size_t)s1 * 128 + lane * 4);
        uint2 r2 = *(const uint2*)(h + (size_t)s2 * 128 + lane * 4);
        uint2 r3 = *(const uint2*)(h + (size_t)s3 * 128 + lane * 4);
        float w0 = g_dinv[s0] * dv, w1 = g_dinv[s1] * dv;
        float w2 = g_dinv[s2] * dv, w3 = g_dinv[s3] * dv;
        ACC1(r0, w0); ACC1(r1, w1); ACC1(r2, w2); ACC1(r3, w3);
    }
    for (; e < end; e++) {
        int sv = g_csrc[e];
        uint2 r = *(const uint2*)(h + (size_t)sv * 128 + lane * 4);
        float w = g_dinv[sv] * dv;
        ACC1(r, w);
    }
    float4 bv = *(const float4*)(bias + lane * 4);
    acc.x += bv.x; acc.y += bv.y; acc.z += bv.z; acc.w += bv.w;
    acc.x = acc.x > 0.f ? acc.x : NEG_SLOPE * acc.x;
    acc.y = acc.y > 0.f ? acc.y : NEG_SLOPE * acc.y;
    acc.z = acc.z > 0.f ? acc.z : NEG_SLOPE * acc.z;
    acc.w = acc.w > 0.f ? acc.w : NEG_SLOPE * acc.w;
    __half2 o0 = __floats2half2_rn(acc.x, acc.y);
    __half2 o1 = __floats2half2_rn(acc.z, acc.w);
    uint2 ov;
    ov.x = *reinterpret_cast<unsigned*>(&o0);
    ov.y = *reinterpret_cast<unsigned*>(&o1);
    *(uint2*)(out + (size_t)warp * 128 + lane * 4) = ov;
}

// ---------------- pool: sorted batch, binary-searched ranges ----------------
__global__ __launch_bounds__(128) void pool_kernel(const __half* __restrict__ act,
                                                   const int* __restrict__ batch)
{
    __shared__ int sbeg, send;
    int g = blockIdx.x;
    int t = threadIdx.x;
    if (t < 2) {
        // lower_bound(batch, g + t): first i with batch[i] >= g + t
        int target = g + t;
        int lo = 0, hi = N_NODES;
        while (lo < hi) {
            int mid = (lo + hi) >> 1;
            if (batch[mid] < target) lo = mid + 1; else hi = mid;
        }
        if (t == 0) sbeg = lo; else send = lo;
    }
    __syncthreads();
    int beg = sbeg, end = send;
    float sum = 0.0f;
    for (int i = beg; i < end; i++) {
        __half v = act[(size_t)i * 128 + t];
        sum += __half2float(v);
    }
    g_pool[g * 128 + t] = sum;
    if (t == 0) g_cnt[g] = (float)(end - beg);
}

// ---------------- final FC ----------------
__global__ void fc_kernel(const float* __restrict__ Wfc, const float* __restrict__ bfc,
                          float* __restrict__ out)
{
    int t = threadIdx.x;
    if (t >= N_GRAPHS * 2) return;
    int g = t >> 1, c = t & 1;
    float inv = 1.0f / fmaxf(g_cnt[g], 1.0f);
    float sum = 0.0f;
    #pragma unroll 4
    for (int k = 0; k < 128; k++)
        sum = fmaf(g_pool[g * 128 + k] * inv, Wfc[k * 2 + c], sum);
    out[t] = sum + bfc[c];
}

// ---------------- launch ----------------
extern "C" void kernel_launch(void* const* d_in, const int* in_sizes, int n_in,
                              void* d_out, int out_size)
{
    const float* x   = (const float*)d_in[0];
    const int*   ei  = (const int*)d_in[1];
    const int*   bat = (const int*)d_in[2];
    const float* W1  = (const float*)d_in[3];
    const float* b1  = (const float*)d_in[4];
    const float* W2  = (const float*)d_in[5];
    const float* b2  = (const float*)d_in[6];
    const float* Wfc = (const float*)d_in[7];
    const float* bfc = (const float*)d_in[8];
    float* out = (float*)d_out;
    const int* src = ei;
    const int* dst = ei + N_EDGES;

    __half *hptr, *aptr;
    cudaGetSymbolAddress((void**)&hptr, g_h);
    cudaGetSymbolAddress((void**)&aptr, g_a);

    const int TB = 256;
    int node_blocks = (N_NODES + TB - 1) / TB;
    int edge_blocks = (N_EDGES + TB - 1) / TB;
    int warp_blocks = (N_NODES * 32 + TB - 1) / TB;
    int gemm_blocks = (N_NODES + 127) / 128;

    zero_kernel<<<node_blocks, TB>>>();
    degree_kernel<<<edge_blocks, TB>>>(dst);
    dinv_kernel<<<node_blocks, TB>>>();
    scan1_kernel<<<NB_SCAN, SCAN_B>>>();
    scan2_kernel<<<1, 128>>>();
    scan3_kernel<<<NB_SCAN, SCAN_B>>>();
    csr_fill_kernel<<<edge_blocks, TB>>>(src, dst);

    // layer 1
    gemm_tc_kernel<float><<<gemm_blocks, TB>>>(x, W1, hptr, N_NODES, F_IN);
    aggregate_kernel<<<warp_blocks, TB>>>(hptr, b1, aptr);
    // layer 2
    gemm_tc_kernel<__half><<<gemm_blocks, TB>>>(aptr, W2, hptr, N_NODES, F_HID);
    aggregate_kernel<<<warp_blocks, TB>>>(hptr, b2, aptr);

    // pool + fc
    pool_kernel<<<N_GRAPHS, 128>>>(aptr, bat);
    fc_kernel<<<1, 128>>>(Wfc, bfc, out);
}

// round 6
// speedup vs baseline: 3.7885x; 1.0827x over previous
#include <cuda_runtime.h>
#include <cuda_fp16.h>
#include <math.h>

#define N_NODES   100000
#define N_EDGES   1600000
#define N_GRAPHS  64
#define F_IN      256
#define F_HID     128
#define NEG_SLOPE 0.01f

#define SCAN_B    1024
#define NB_SCAN   ((N_NODES + SCAN_B - 1) / SCAN_B)   // 98

// ---------------- scratch ----------------
__device__ __half g_h[(size_t)N_NODES * F_HID];   // GEMM output (fp16)
__device__ __half g_a[(size_t)N_NODES * F_HID];   // aggregate output (fp16)
__device__ int    g_deg[N_NODES];
__device__ int    g_fill[N_NODES];
__device__ float  g_dinv[N_NODES];
__device__ int    g_rowptr[N_NODES + 1];
__device__ int    g_csrc[N_EDGES];
__device__ int    g_bsum[NB_SCAN];
__device__ int    g_boff[NB_SCAN];
__device__ float  g_pool[N_GRAPHS * F_HID];
__device__ float  g_cnt[N_GRAPHS];

// ---------------- init ----------------
__global__ void zero_kernel() {
    int i = blockIdx.x * blockDim.x + threadIdx.x;
    if (i < N_NODES) { g_deg[i] = 0; g_fill[i] = 0; }
}

// ---------------- degree ----------------
__global__ void degree_kernel(const int* __restrict__ dst) {
    int e = blockIdx.x * blockDim.x + threadIdx.x;
    if (e < N_EDGES) atomicAdd(&g_deg[dst[e]], 1);
}

__global__ void dinv_kernel() {
    int i = blockIdx.x * blockDim.x + threadIdx.x;
    if (i < N_NODES) g_dinv[i] = rsqrtf((float)g_deg[i] + 1.0f);
}

// ---------------- parallel exclusive scan: deg -> rowptr ----------------
__global__ __launch_bounds__(SCAN_B) void scan1_kernel() {
    __shared__ int red[SCAN_B];
    int t = threadIdx.x;
    int i = blockIdx.x * SCAN_B + t;
    red[t] = (i < N_NODES) ? g_deg[i] : 0;
    __syncthreads();
    for (int off = SCAN_B / 2; off > 0; off >>= 1) {
        if (t < off) red[t] += red[t + off];
        __syncthreads();
    }
    if (t == 0) g_bsum[blockIdx.x] = red[0];
}

__global__ void scan2_kernel() {
    __shared__ int s[NB_SCAN];
    int t = threadIdx.x;
    if (t < NB_SCAN) s[t] = g_bsum[t];
    __syncthreads();
    if (t == 0) {
        int run = 0;
        for (int b = 0; b < NB_SCAN; b++) { int v = s[b]; s[b] = run; run += v; }
        g_rowptr[N_NODES] = N_EDGES;
    }
    __syncthreads();
    if (t < NB_SCAN) g_boff[t] = s[t];
}

__global__ __launch_bounds__(SCAN_B) void scan3_kernel() {
    __shared__ int s[SCAN_B];
    int t = threadIdx.x;
    int i = blockIdx.x * SCAN_B + t;
    int v = (i < N_NODES) ? g_deg[i] : 0;
    s[t] = v;
    __syncthreads();
    for (int off = 1; off < SCAN_B; off <<= 1) {
        int u = (t >= off) ? s[t - off] : 0;
        __syncthreads();
        s[t] += u;
        __syncthreads();
    }
    if (i < N_NODES) g_rowptr[i] = g_boff[blockIdx.x] + s[t] - v;
}

// ---------------- CSR fill ----------------
__global__ void csr_fill_kernel(const int* __restrict__ src, const int* __restrict__ dst) {
    int e = blockIdx.x * blockDim.x + threadIdx.x;
    if (e < N_EDGES) {
        int d = dst[e];
        int pos = g_rowptr[d] + atomicAdd(&g_fill[d], 1);
        g_csrc[pos] = src[e];
    }
}

// ---------------- FP16 tensor-core GEMM: C[M,128] = A[M,K] @ B[K,128], C fp16 ----------------
// mma.m16n8k16.f16 with fp32 accum. BM=128, BN=128, BK=16, double-buffered.
// 8 warps, 2(m) x 4(n), warp tile 64x32.
// A smem: half2 words [m][12] (8 used), conflict-free (pad 12: g*12+t bijective mod 32).
// B smem: half2 words [k2][136] (128 used), conflict-free (136 = 8 mod 32).

__device__ __forceinline__ void mma_f16(float* c, const unsigned* a, const unsigned* b) {
    asm volatile(
        "mma.sync.aligned.m16n8k16.row.col.f32.f16.f16.f32 "
        "{%0,%1,%2,%3}, {%4,%5,%6,%7}, {%8,%9}, {%0,%1,%2,%3};\n"
        : "+f"(c[0]), "+f"(c[1]), "+f"(c[2]), "+f"(c[3])
        : "r"(a[0]), "r"(a[1]), "r"(a[2]), "r"(a[3]), "r"(b[0]), "r"(b[1]));
}

#define A2PAD 12
#define B2PAD 136

__device__ __forceinline__ unsigned h2u(__half2 h) {
    return *reinterpret_cast<unsigned*>(&h);
}

// load 16 consecutive k-elements of A as 4 packed half2 words
__device__ __forceinline__ void load_a16(const float* p, bool ok, unsigned v[4]) {
    float4 a0 = make_float4(0,0,0,0), a1 = make_float4(0,0,0,0);
    if (ok) { a0 = *(const float4*)p; a1 = *(const float4*)(p + 4); }
    v[0] = h2u(__floats2half2_rn(a0.x, a0.y));
    v[1] = h2u(__floats2half2_rn(a0.z, a0.w));
    v[2] = h2u(__floats2half2_rn(a1.x, a1.y));
    v[3] = h2u(__floats2half2_rn(a1.z, a1.w));
}

__device__ __forceinline__ void load_a16(const __half* p, bool ok, unsigned v[4]) {
    uint4 raw = make_uint4(0,0,0,0);
    if (ok) raw = *(const uint4*)p;
    v[0] = raw.x; v[1] = raw.y; v[2] = raw.z; v[3] = raw.w;
}

template <typename TA>
__global__ __launch_bounds__(256) void gemm_tc_kernel(
    const TA* __restrict__ A, const float* __restrict__ B,
    __half* __restrict__ C, int M, int K)
{
    __shared__ unsigned As[2][128][A2PAD];  // half2 words, 8 of 12 used per row
    __shared__ unsigned Bs[2][8][B2PAD];    // half2 words: Bs[j][n] = {B[2j][n], B[2j+1][n]}

    const int tid  = threadIdx.x;
    const int warp = tid >> 5;
    const int lane = tid & 31;
    const int g    = lane >> 2;
    const int t    = lane & 3;
    const int m0   = (warp >> 2) * 64;
    const int n0   = (warp & 3) * 32;
    const int block_m = blockIdx.x * 128;

    // A global load: 2 threads per row, 8 elements each -> one uint4 smem store
    const int arow = tid >> 1;
    const int acol = (tid & 1) * 8;          // element offset
    const int aword = (tid & 1) * 4;         // half2-word offset
    // B global load: 8 k-pairs x 32 n-quads
    const int bj   = tid >> 5;               // 0..7 (k-pair index)
    const int bn   = (tid & 31) * 4;         // n offset (floats/words)

    const int gm_a = block_m + arow;
    const bool a_ok = (gm_a < M);
    const TA* Ap = A + (size_t)gm_a * K + acol;
    const float* Bp0 = B + (size_t)(2 * bj) * 128 + bn;
    const float* Bp1 = B + (size_t)(2 * bj + 1) * 128 + bn;

    float acc[4][4][4];
    #pragma unroll
    for (int i = 0; i < 4; i++)
        #pragma unroll
        for (int j = 0; j < 4; j++)
            #pragma unroll
            for (int v = 0; v < 4; v++) acc[i][j][v] = 0.0f;

    // preload tile 0
    {
        unsigned av[4];
        load_a16(Ap, a_ok, av);
        *(uint4*)&As[0][arow][aword] = make_uint4(av[0], av[1], av[2], av[3]);
        float4 u = *(const float4*)Bp0;
        float4 v = *(const float4*)Bp1;
        uint4 bw;
        bw.x = h2u(__floats2half2_rn(u.x, v.x));
        bw.y = h2u(__floats2half2_rn(u.y, v.y));
        bw.z = h2u(__floats2half2_rn(u.z, v.z));
        bw.w = h2u(__floats2half2_rn(u.w, v.w));
        *(uint4*)&Bs[0][bj][bn] = bw;
    }
    __syncthreads();

    int buf = 0;
    for (int k0 = 0; k0 < K; k0 += 16) {
        const bool more = (k0 + 16 < K);
        unsigned av[4];
        uint4 bw;
        if (more) {
            load_a16(Ap + k0 + 16, a_ok, av);
            float4 u = *(const float4*)(Bp0 + (size_t)(k0 + 16) * 128);
            float4 v = *(const float4*)(Bp1 + (size_t)(k0 + 16) * 128);
            bw.x = h2u(__floats2half2_rn(u.x, v.x));
            bw.y = h2u(__floats2half2_rn(u.y, v.y));
            bw.z = h2u(__floats2half2_rn(u.z, v.z));
            bw.w = h2u(__floats2half2_rn(u.w, v.w));
        }

        // compute on current tile: one m16n8k16 per (mf, nf)
        {
            unsigned bfr[4][2];
            #pragma unroll
            for (int nf = 0; nf < 4; nf++) {
                int n = n0 + nf * 8 + g;
                bfr[nf][0] = Bs[buf][t][n];
                bfr[nf][1] = Bs[buf][t + 4][n];
            }
            #pragma unroll
            for (int mf = 0; mf < 4; mf++) {
                int r = m0 + mf * 16 + g;
                unsigned afr[4];
                afr[0] = As[buf][r][t];
                afr[1] = As[buf][r + 8][t];
                afr[2] = As[buf][r][t + 4];
                afr[3] = As[buf][r + 8][t + 4];
                #pragma unroll
                for (int nf = 0; nf < 4; nf++)
                    mma_f16(acc[mf][nf], afr, bfr[nf]);
            }
        }

        if (more) {
            int nb = buf ^ 1;
            *(uint4*)&As[nb][arow][aword] = make_uint4(av[0], av[1], av[2], av[3]);
            *(uint4*)&Bs[nb][bj][bn] = bw;
            __syncthreads();
            buf = nb;
        }
    }

    // epilogue: fp16 stores
    #pragma unroll
    for (int mf = 0; mf < 4; mf++) {
        int r0 = block_m + m0 + mf * 16 + g;
        int r1 = r0 + 8;
        #pragma unroll
        for (int nf = 0; nf < 4; nf++) {
            int col = n0 + nf * 8 + t * 2;
            if (r0 < M)
                *(__half2*)(C + (size_t)r0 * 128 + col) =
                    __floats2half2_rn(acc[mf][nf][0], acc[mf][nf][1]);
            if (r1 < M)
                *(__half2*)(C + (size_t)r1 * 128 + col) =
                    __floats2half2_rn(acc[mf][nf][2], acc[mf][nf][3]);
        }
    }
}

// ---------------- aggregation: warp/node, fp16 gather, unroll 8, fp16 out ----------------
#define ACC1(R, W)                                                           \
    {                                                                        \
        float2 _a = __half22float2(*reinterpret_cast<__half2*>(&(R).x));     \
        float2 _b = __half22float2(*reinterpret_cast<__half2*>(&(R).y));     \
        acc.x = fmaf(_a.x, (W), acc.x); acc.y = fmaf(_a.y, (W), acc.y);      \
        acc.z = fmaf(_b.x, (W), acc.z); acc.w = fmaf(_b.y, (W), acc.w);      \
    }

__global__ __launch_bounds__(256) void aggregate_kernel(
    const __half* __restrict__ h, const float* __restrict__ bias,
    __half* __restrict__ out)
{
    int warp = (blockIdx.x * blockDim.x + threadIdx.x) >> 5;
    int lane = threadIdx.x & 31;
    if (warp >= N_NODES) return;
    float dv = g_dinv[warp];
    float4 acc = make_float4(0.f, 0.f, 0.f, 0.f);
    {   // self loop
        uint2 r = *(const uint2*)(h + (size_t)warp * 128 + lane * 4);
        float w = dv * dv;
        ACC1(r, w);
    }
    int e = g_rowptr[warp], end = g_rowptr[warp + 1];

    for (; e + 8 <= end; e += 8) {
        int s0 = g_csrc[e+0], s1 = g_csrc[e+1], s2 = g_csrc[e+2], s3 = g_csrc[e+3];
        int s4 = g_csrc[e+4], s5 = g_csrc[e+5], s6 = g_csrc[e+6], s7 = g_csrc[e+7];
        uint2 r0 = *(const uint2*)(h + (size_t)s0 * 128 + lane * 4);
        uint2 r1 = *(const uint2*)(h + (size_t)s1 * 128 + lane * 4);
        uint2 r2 = *(const uint2*)(h + (size_t)s2 * 128 + lane * 4);
        uint2 r3 = *(const uint2*)(h + (size_t)s3 * 128 + lane * 4);
        uint2 r4 = *(const uint2*)(h + (size_t)s4 * 128 + lane * 4);
        uint2 r5 = *(const uint2*)(h + (size_t)s5 * 128 + lane * 4);
        uint2 r6 = *(const uint2*)(h + (size_t)s6 * 128 + lane * 4);
        uint2 r7 = *(const uint2*)(h + (size_t)s7 * 128 + lane * 4);
        float w0 = g_dinv[s0] * dv, w1 = g_dinv[s1] * dv;
        float w2 = g_dinv[s2] * dv, w3 = g_dinv[s3] * dv;
        float w4 = g_dinv[s4] * dv, w5 = g_dinv[s5] * dv;
        float w6 = g_dinv[s6] * dv, w7 = g_dinv[s7] * dv;
        ACC1(r0, w0); ACC1(r1, w1); ACC1(r2, w2); ACC1(r3, w3);
        ACC1(r4, w4); ACC1(r5, w5); ACC1(r6, w6); ACC1(r7, w7);
    }
    for (; e + 4 <= end; e += 4) {
        int s0 = g_csrc[e+0], s1 = g_csrc[e+1], s2 = g_csrc[e+2], s3 = g_csrc[e+3];
        uint2 r0 = *(const uint2*)(h + (size_t)s0 * 128 + lane * 4);
        uint2 r1 = *(const uint2*)(h + (size_t)s1 * 128 + lane * 4);
        uint2 r2 = *(const uint2*)(h + (size_t)s2 * 128 + lane * 4);
        uint2 r3 = *(const uint2*)(h + (size_t)s3 * 128 + lane * 4);
        float w0 = g_dinv[s0] * dv, w1 = g_dinv[s1] * dv;
        float w2 = g_dinv[s2] * dv, w3 = g_dinv[s3] * dv;
        ACC1(r0, w0); ACC1(r1, w1); ACC1(r2, w2); ACC1(r3, w3);
    }
    for (; e < end; e++) {
        int sv = g_csrc[e];
        uint2 r = *(const uint2*)(h + (size_t)sv * 128 + lane * 4);
        float w = g_dinv[sv] * dv;
        ACC1(r, w);
    }
    float4 bv = *(const float4*)(bias + lane * 4);
    acc.x += bv.x; acc.y += bv.y; acc.z += bv.z; acc.w += bv.w;
    acc.x = acc.x > 0.f ? acc.x : NEG_SLOPE * acc.x;
    acc.y = acc.y > 0.f ? acc.y : NEG_SLOPE * acc.y;
    acc.z = acc.z > 0.f ? acc.z : NEG_SLOPE * acc.z;
    acc.w = acc.w > 0.f ? acc.w : NEG_SLOPE * acc.w;
    __half2 o0 = __floats2half2_rn(acc.x, acc.y);
    __half2 o1 = __floats2half2_rn(acc.z, acc.w);
    uint2 ov;
    ov.x = *reinterpret_cast<unsigned*>(&o0);
    ov.y = *reinterpret_cast<unsigned*>(&o1);
    *(uint2*)(out + (size_t)warp * 128 + lane * 4) = ov;
}

// ---------------- pool: sorted batch, binary-searched ranges ----------------
__global__ __launch_bounds__(128) void pool_kernel(const __half* __restrict__ act,
                                                   const int* __restrict__ batch)
{
    __shared__ int sbeg, send;
    int g = blockIdx.x;
    int t = threadIdx.x;
    if (t < 2) {
        int target = g + t;
        int lo = 0, hi = N_NODES;
        while (lo < hi) {
            int mid = (lo + hi) >> 1;
            if (batch[mid] < target) lo = mid + 1; else hi = mid;
        }
        if (t == 0) sbeg = lo; else send = lo;
    }
    __syncthreads();
    int beg = sbeg, end = send;
    float sum = 0.0f;
    for (int i = beg; i < end; i++) {
        __half v = act[(size_t)i * 128 + t];
        sum += __half2float(v);
    }
    g_pool[g * 128 + t] = sum;
    if (t == 0) g_cnt[g] = (float)(end - beg);
}

// ---------------- final FC ----------------
__global__ void fc_kernel(const float* __restrict__ Wfc, const float* __restrict__ bfc,
                          float* __restrict__ out)
{
    int t = threadIdx.x;
    if (t >= N_GRAPHS * 2) return;
    int g = t >> 1, c = t & 1;
    float inv = 1.0f / fmaxf(g_cnt[g], 1.0f);
    float sum = 0.0f;
    #pragma unroll 4
    for (int k = 0; k < 128; k++)
        sum = fmaf(g_pool[g * 128 + k] * inv, Wfc[k * 2 + c], sum);
    out[t] = sum + bfc[c];
}

// ---------------- launch ----------------
extern "C" void kernel_launch(void* const* d_in, const int* in_sizes, int n_in,
                              void* d_out, int out_size)
{
    const float* x   = (const float*)d_in[0];
    const int*   ei  = (const int*)d_in[1];
    const int*   bat = (const int*)d_in[2];
    const float* W1  = (const float*)d_in[3];
    const float* b1  = (const float*)d_in[4];
    const float* W2  = (const float*)d_in[5];
    const float* b2  = (const float*)d_in[6];
    const float* Wfc = (const float*)d_in[7];
    const float* bfc = (const float*)d_in[8];
    float* out = (float*)d_out;
    const int* src = ei;
    const int* dst = ei + N_EDGES;

    __half *hptr, *aptr;
    cudaGetSymbolAddress((void**)&hptr, g_h);
    cudaGetSymbolAddress((void**)&aptr, g_a);

    const int TB = 256;
    int node_blocks = (N_NODES + TB - 1) / TB;
    int edge_blocks = (N_EDGES + TB - 1) / TB;
    int warp_blocks = (N_NODES * 32 + TB - 1) / TB;
    int gemm_blocks = (N_NODES + 127) / 128;

    zero_kernel<<<node_blocks, TB>>>();
    degree_kernel<<<edge_blocks, TB>>>(dst);
    dinv_kernel<<<node_blocks, TB>>>();
    scan1_kernel<<<NB_SCAN, SCAN_B>>>();
    scan2_kernel<<<1, 128>>>();
    scan3_kernel<<<NB_SCAN, SCAN_B>>>();
    csr_fill_kernel<<<edge_blocks, TB>>>(src, dst);

    // layer 1
    gemm_tc_kernel<float><<<gemm_blocks, TB>>>(x, W1, hptr, N_NODES, F_IN);
    aggregate_kernel<<<warp_blocks, TB>>>(hptr, b1, aptr);
    // layer 2
    gemm_tc_kernel<__half><<<gemm_blocks, TB>>>(aptr, W2, hptr, N_NODES, F_HID);
    aggregate_kernel<<<warp_blocks, TB>>>(hptr, b2, aptr);

    // pool + fc
    pool_kernel<<<N_GRAPHS, 128>>>(aptr, bat);
    fc_kernel<<<1, 128>>>(Wfc, bfc, out);
}